// round 9
// baseline (speedup 1.0000x reference)
#include <cuda_runtime.h>
#include <cuda_bf16.h>

#define BQ 256
#define DD 256
#define NBANK 100000
#define NPAD 100096
#define TN 128
#define NUM_TILES ((NBANK + TN - 1) / TN)      // 782
#define NCH 8
#define KCH 32
#define SR 80                                   // smem row stride (64B data + 16B pad)
#define THREADS 256

typedef unsigned long long ull;
typedef unsigned int u32;

// --------------- device scratch --------------------------------------------
__device__ ull    g_aP[BQ];                     // approx masked min (primary)
__device__ ull    g_aF[BQ];                     // approx masked min (fallback)
__device__ ull    g_ex[BQ];                     // exact rescored min
__device__ float  g_thr[BQ];
__device__ int    g_hasP[BQ];
__device__ float  g_a2[BQ];
__device__ int    g_b2maxI;
__device__ uint4  g_Q[NCH][BQ][4];              // hi-split queries
__device__ uint4  g_bankH[(size_t)NPAD * 32];   // bf16 hi bank image
__device__ float  g_b2[NPAD];
__device__ float4 g_scores[(size_t)NUM_TILES * THREADS * 32];  // 102.5MB raw scores

// --------------- smem layout (phase A) --------------------------------------
#define QBUF  (BQ * SR)                     // 20480
#define BBUF  (TN * SR)                     // 10240
#define OFF_Q    0                          // [2 buf][256][SR]
#define OFF_B    (2 * QBUF)                 // 40960: [2 buf][128][SR]
#define OFF_RED  (OFF_B + 2 * BBUF)         // 61440
#define OFF_B2S  (OFF_RED + 2 * BQ * 8)     // 65536
#define OFF_SCLU (OFF_B2S + 512)
#define OFF_SCLS (OFF_SCLU + 512)
#define OFF_SCID (OFF_SCLS + 512)
#define OFF_SGT  (OFF_SCID + 1024)
#define SMEM_TOTAL (OFF_SGT + 1024)         // 69120

// --------------- helpers -----------------------------------------------------
__device__ __forceinline__ u32 smem_u32(const void* p) {
    u32 a;
    asm("{ .reg .u64 t; cvta.to.shared.u64 t, %1; cvt.u32.u64 %0, t; }" : "=r"(a) : "l"(p));
    return a;
}
#define LDSM_X4(r, addr) \
    asm volatile("ldmatrix.sync.aligned.m8n8.x4.shared.b16 {%0,%1,%2,%3}, [%4];" \
        : "=r"((r)[0]), "=r"((r)[1]), "=r"((r)[2]), "=r"((r)[3]) : "r"(addr))
#define MMA16816(d, a, b0, b1) \
    asm volatile("mma.sync.aligned.m16n8k16.row.col.f32.bf16.bf16.f32 " \
        "{%0,%1,%2,%3}, {%4,%5,%6,%7}, {%8,%9}, {%0,%1,%2,%3};" \
        : "+f"((d)[0]), "+f"((d)[1]), "+f"((d)[2]), "+f"((d)[3]) \
        : "r"((a)[0]), "r"((a)[1]), "r"((a)[2]), "r"((a)[3]), "r"(b0), "r"(b1))
#define CP_ASYNC16(dst, src) \
    asm volatile("cp.async.cg.shared.global [%0], [%1], 16;" :: "r"(dst), "l"(src) : "memory")
#define CP_COMMIT() asm volatile("cp.async.commit_group;" ::: "memory")
#define CP_WAIT0()  asm volatile("cp.async.wait_group 0;" ::: "memory")

__device__ __forceinline__ ull encode(float f, int n) {
    u32 u = __float_as_uint(f);
    u = (u & 0x80000000u) ? ~u : (u | 0x80000000u);
    return ((ull)u << 32) | (u32)n;
}
__device__ __forceinline__ float decode_hi(ull e) {
    u32 u = (u32)(e >> 32);
    u = (u & 0x80000000u) ? (u ^ 0x80000000u) : ~u;
    return __uint_as_float(u);
}
__device__ __forceinline__ u32 hi2(float a0, float a1) {
    __nv_bfloat16 h0 = __float2bfloat16(a0);
    __nv_bfloat16 h1 = __float2bfloat16(a1);
    return (u32)__bfloat16_as_ushort(h0) | ((u32)__bfloat16_as_ushort(h1) << 16);
}

// ---------------------------------------------------------------------------
// prep: grid NCH blocks; block c splits chunk c of all queries. Block 0 also
// computes a2 per query, inits approx-min arrays and b2max.
// ---------------------------------------------------------------------------
__global__ void prep_kernel(const float* __restrict__ feat) {
    int c = blockIdx.x, q = threadIdx.x;
    const float* row = feat + q * DD;
    if (c == 0) {
        g_aP[q] = ~0ULL;
        g_aF[q] = ~0ULL;
        float s = 0.f;
        for (int k = 0; k < DD; ++k) s = fmaf(row[k], row[k], s);
        g_a2[q] = s;
        if (q == 0) g_b2maxI = 0;
    }
#pragma unroll
    for (int i = 0; i < 4; ++i) {
        u32 H[4];
#pragma unroll
        for (int e = 0; e < 8; e += 2) {
            int k = c * KCH + i * 8 + e;
            H[e >> 1] = hi2(row[k], row[k + 1]);
        }
        g_Q[c][q][i] = make_uint4(H[0], H[1], H[2], H[3]);
    }
}

// ---------------------------------------------------------------------------
// convert: bank fp32 -> bf16 hi image + exact b2 + global b2max.
// ---------------------------------------------------------------------------
__global__ void __launch_bounds__(256) convert_kernel(const float* __restrict__ bank) {
    int row = blockIdx.x * 8 + (threadIdx.x >> 5);
    if (row >= NBANK) return;
    int lane = threadIdx.x & 31;
    const float4* src = (const float4*)(bank + (size_t)row * DD) + lane * 2;
    float4 v0 = src[0], v1 = src[1];
    float vv[8] = {v0.x, v0.y, v0.z, v0.w, v1.x, v1.y, v1.z, v1.w};
    u32 H[4];
    float s = 0.f;
#pragma unroll
    for (int e = 0; e < 8; e += 2) {
        s = fmaf(vv[e], vv[e], s);
        s = fmaf(vv[e + 1], vv[e + 1], s);
        H[e >> 1] = hi2(vv[e], vv[e + 1]);
    }
    g_bankH[(size_t)row * 32 + lane] = make_uint4(H[0], H[1], H[2], H[3]);
#pragma unroll
    for (int o = 16; o; o >>= 1) s += __shfl_xor_sync(0xffffffffu, s, o);
    if (lane == 0) {
        g_b2[row] = s;
        atomicMax(&g_b2maxI, __float_as_int(s));   // s > 0, int compare valid
    }
}

// ---------------------------------------------------------------------------
__device__ __forceinline__ void stage_chunk(u32 smb, int buf, int c, int tid, int n0) {
    // Q: 1024 16B pieces (256 rows x 4 segs), 4 per thread
#pragma unroll
    for (int p = 0; p < 4; ++p) {
        int idx = tid + THREADS * p;
        int row = idx >> 2, seg = idx & 3;
        CP_ASYNC16(smb + OFF_Q + (u32)buf * QBUF + (u32)row * SR + (u32)seg * 16,
                   &g_Q[c][row][seg]);
    }
    // B: 512 pieces (128 rows x 4 segs), 2 per thread
#pragma unroll
    for (int p = 0; p < 2; ++p) {
        int idx = tid + THREADS * p;
        int rw = idx >> 2, seg = idx & 3;
        CP_ASYNC16(smb + OFF_B + (u32)buf * BBUF + (u32)rw * SR + (u32)seg * 16,
                   g_bankH + (size_t)(n0 + rw) * 32 + c * 4 + seg);
    }
}

// ---------------------------------------------------------------------------
// Phase A: hi-only bf16 HMMA GEMM (128 bank rows x 256 q per CTA, 8 warps,
// warp tile 64q x 64n). Stores raw approx scores + masked approx argmins.
// ---------------------------------------------------------------------------
__global__ void __launch_bounds__(THREADS, 1) main_kernel(
    const int* __restrict__ cluL, const int* __restrict__ clsL,
    const int* __restrict__ cid,  const int* __restrict__ gt)
{
    extern __shared__ char sm[];
    const u32 smb  = smem_u32(sm);
    const int tid  = threadIdx.x;
    const int lane = tid & 31;
    const int w    = tid >> 5;
    const int n0   = blockIdx.x * TN;

    ull*   redP = (ull*)(sm + OFF_RED);
    ull*   redF = redP + BQ;
    float* b2s  = (float*)(sm + OFF_B2S);
    int*   sClu = (int*)(sm + OFF_SCLU);
    int*   sCls = (int*)(sm + OFF_SCLS);
    int*   sCid = (int*)(sm + OFF_SCID);
    int*   sGt  = (int*)(sm + OFF_SGT);

    stage_chunk(smb, 0, 0, tid, n0);
    CP_COMMIT();

    redP[tid] = ~0ULL;
    redF[tid] = ~0ULL;
    sCid[tid] = cid[tid];
    sGt[tid]  = gt[tid];
    if (tid < TN) {
        int n = n0 + tid;
        bool v = (n < NBANK);
        sClu[tid] = v ? cluL[n] : -1;
        sCls[tid] = v ? clsL[n] : 0x7fffffff;
        b2s[tid]  = v ? g_b2[n] : __int_as_float(0x7f800000);   // +inf for pad rows
    }

    const int q0 = (w & 3) * 64;
    const int nh = (w >> 2) * 64;

    float acc[4][8][4];
#pragma unroll
    for (int mi = 0; mi < 4; mi++)
#pragma unroll
        for (int nt = 0; nt < 8; nt++)
#pragma unroll
            for (int r = 0; r < 4; r++) acc[mi][nt][r] = 0.f;

    const u32 aRowOff = (u32)(q0 + (lane & 15)) * SR + (u32)(lane >> 4) * 16;
    const int bRow    = nh + ((lane >> 4) & 1) * 8 + (lane & 7);
    const u32 bColB   = ((lane >> 3) & 1) * 16;

#pragma unroll 1
    for (int c = 0; c < NCH; ++c) {
        CP_WAIT0();
        __syncthreads();
        if (c + 1 < NCH) { stage_chunk(smb, (c + 1) & 1, c + 1, tid, n0); CP_COMMIT(); }

        const int buf = c & 1;
        const u32 qH = smb + OFF_Q + (u32)buf * QBUF + aRowOff;
        const u32 bH = smb + OFF_B + (u32)buf * BBUF;
#pragma unroll
        for (int kk = 0; kk < KCH; kk += 16) {
            const u32 kb = (u32)kk * 2 + bColB;
            u32 aH[4][4];
#pragma unroll
            for (int mi = 0; mi < 4; mi++) LDSM_X4(aH[mi], qH + mi * 16 * SR + kk * 2);
            u32 bB[16];
#pragma unroll
            for (int p = 0; p < 4; p++)
                LDSM_X4(&bB[4 * p], bH + (u32)(bRow + p * 16) * SR + kb);
#pragma unroll
            for (int mi = 0; mi < 4; mi++)
#pragma unroll
                for (int nt = 0; nt < 8; nt++)
                    MMA16816(acc[mi][nt], aH[mi], bB[2 * nt], bB[2 * nt + 1]);
        }
    }

    // ---- epilogue: store raw scores + masked approx dual argmin ----
    {
        const int jb = nh + 2 * (lane & 3);
        float4* out = g_scores + ((size_t)blockIdx.x * THREADS + tid) * 32;
        float b2r[16]; int clsr[16], clur[16]; bool val[16];
#pragma unroll
        for (int ni = 0; ni < 8; ni++)
#pragma unroll
            for (int h = 0; h < 2; h++) {
                int j = jb - nh + 8 * ni + h + nh;   // = jb + 8*ni + h
                int x = ni * 2 + h;
                b2r[x]  = b2s[j];
                clsr[x] = sCls[j];
                clur[x] = sClu[j];
                val[x]  = (n0 + j) < NBANK;
            }
#pragma unroll
        for (int mi = 0; mi < 4; mi++) {
            // raw score store (no masking; pad rows carry +inf)
#pragma unroll
            for (int ni = 0; ni < 8; ni++) {
                float s0 = fmaf(-2.f, acc[mi][ni][0], b2r[ni * 2 + 0]);
                float s1 = fmaf(-2.f, acc[mi][ni][1], b2r[ni * 2 + 1]);
                float s2 = fmaf(-2.f, acc[mi][ni][2], b2r[ni * 2 + 0]);
                float s3 = fmaf(-2.f, acc[mi][ni][3], b2r[ni * 2 + 1]);
                out[mi * 8 + ni] = make_float4(s0, s1, s2, s3);
            }
#pragma unroll
            for (int half = 0; half < 2; half++) {
                int r = q0 + mi * 16 + (lane >> 2) + 8 * half;
                int gtq = sGt[r], ciq = sCid[r];
                ull bp = ~0ULL, bf = ~0ULL;
#pragma unroll
                for (int ni = 0; ni < 8; ni++)
#pragma unroll
                    for (int h = 0; h < 2; h++) {
                        int x = ni * 2 + h;
                        if (!val[x] || clsr[x] == gtq) continue;
                        float score = fmaf(-2.f, acc[mi][ni][half * 2 + h], b2r[x]);
                        ull e = encode(score, n0 + jb + 8 * ni + h);
                        if (e < bf) bf = e;
                        if (clur[x] == ciq && e < bp) bp = e;
                    }
#pragma unroll
                for (int o = 1; o <= 2; o <<= 1) {
                    ull tp = __shfl_xor_sync(0xffffffffu, bp, o);
                    ull tf = __shfl_xor_sync(0xffffffffu, bf, o);
                    if (tp < bp) bp = tp;
                    if (tf < bf) bf = tf;
                }
                if ((lane & 3) == 0) {
                    if (bp != ~0ULL) atomicMin(&redP[r], bp);
                    if (bf != ~0ULL) atomicMin(&redF[r], bf);
                }
            }
        }
    }
    __syncthreads();
    {
        ull p = redP[tid], f = redF[tid];
        if (p != ~0ULL) atomicMin(&g_aP[tid], p);
        if (f != ~0ULL) atomicMin(&g_aF[tid], f);
    }
}

// ---------------------------------------------------------------------------
// thresh: per-query rescore threshold = approxMin + 2*margin, margin from the
// deterministic bf16 rounding bound 2^-7*sqrt(a2*b2max) (score-space, x1.05).
// ---------------------------------------------------------------------------
__global__ void thresh_kernel() {
    int q = threadIdx.x;
    float b2m = __int_as_float(g_b2maxI);
    float m = 0.0078125f * 1.05f * sqrtf(g_a2[q] * b2m) + 0.02f;
    bool hasP = (g_aP[q] != ~0ULL);
    float amin = hasP ? decode_hi(g_aP[q]) : decode_hi(g_aF[q]);
    g_thr[q]  = amin + 2.f * m;
    g_hasP[q] = hasP ? 1 : 0;
    g_ex[q]   = ~0ULL;
}

// ---------------------------------------------------------------------------
// scan: stream the 102MB score buffer; rare under-threshold hits get an exact
// fp32 rescore (masked) and atomicMin into g_ex.
// ---------------------------------------------------------------------------
__global__ void __launch_bounds__(THREADS) scan_kernel(
    const float* __restrict__ feat, const float* __restrict__ bank,
    const int* __restrict__ cluL, const int* __restrict__ clsL,
    const int* __restrict__ cid,  const int* __restrict__ gt)
{
    __shared__ float sThr[BQ];
    __shared__ int   sHasP[BQ], sCid[BQ], sGt[BQ];
    int tid = threadIdx.x;
    sThr[tid]  = g_thr[tid];
    sHasP[tid] = g_hasP[tid];
    sCid[tid]  = cid[tid];
    sGt[tid]   = gt[tid];
    __syncthreads();

    const int lane = tid & 31, w = tid >> 5;
    const int q0 = (w & 3) * 64, nh = (w >> 2) * 64;
    const int n0 = blockIdx.x * TN;
    const float4* in = g_scores + ((size_t)blockIdx.x * THREADS + tid) * 32;

#pragma unroll 1
    for (int mi = 0; mi < 4; mi++) {
        int qbase = q0 + mi * 16 + (lane >> 2);
#pragma unroll 1
        for (int ni = 0; ni < 8; ni++) {
            float4 s = in[mi * 8 + ni];
            float sv[4] = {s.x, s.y, s.z, s.w};
#pragma unroll
            for (int r = 0; r < 4; r++) {
                int q = qbase + 8 * (r >> 1);
                if (!(sv[r] <= sThr[q])) continue;
                int n = n0 + nh + 2 * (lane & 3) + 8 * ni + (r & 1);
                if (n >= NBANK) continue;
                int cls = clsL[n];
                if (cls == sGt[q]) continue;
                if (sHasP[q] && cluL[n] != sCid[q]) continue;
                // exact fp32 rescore
                const float4* fa = (const float4*)(feat + (size_t)q * DD);
                const float4* fb = (const float4*)(bank + (size_t)n * DD);
                float d = 0.f;
#pragma unroll 16
                for (int k = 0; k < DD / 4; ++k) {
                    float4 a = fa[k], b = fb[k];
                    d = fmaf(a.x, b.x, d);
                    d = fmaf(a.y, b.y, d);
                    d = fmaf(a.z, b.z, d);
                    d = fmaf(a.w, b.w, d);
                }
                float ex = fmaf(-2.f, d, g_b2[n]);
                atomicMin(&g_ex[q], encode(ex, n));
            }
        }
    }
}

// ---------------------------------------------------------------------------
__global__ void gather_kernel(const float* __restrict__ bank, float* __restrict__ out) {
    int b = blockIdx.x;
    ull e = g_ex[b];
    int idx = (e == ~0ULL) ? 0 : (int)(u32)(e & 0xffffffffu);
    const float4* src = (const float4*)(bank + (size_t)idx * DD);
    float4*       dst = (float4*)(out + (size_t)b * DD);
    dst[threadIdx.x] = src[threadIdx.x];
}

__global__ void noop_kernel() {}   // keeps main_kernel at launch #4 for ncu

// ---------------------------------------------------------------------------
extern "C" void kernel_launch(void* const* d_in, const int* in_sizes, int n_in,
                              void* d_out, int out_size) {
    const float* feature = (const float*)d_in[0];
    const float* bank    = (const float*)d_in[1];
    const int*   cluL    = (const int*)d_in[2];
    const int*   clsL    = (const int*)d_in[3];
    const int*   cid     = (const int*)d_in[4];
    const int*   gtl     = (const int*)d_in[5];

    cudaFuncSetAttribute(main_kernel,
                         cudaFuncAttributeMaxDynamicSharedMemorySize, SMEM_TOTAL);

    prep_kernel<<<NCH, BQ>>>(feature);                      // #1
    convert_kernel<<<(NBANK + 7) / 8, 256>>>(bank);         // #2
    noop_kernel<<<1, 32>>>();                               // #3
    main_kernel<<<NUM_TILES, THREADS, SMEM_TOTAL>>>(cluL, clsL, cid, gtl);  // #4 (ncu)
    thresh_kernel<<<1, BQ>>>();                             // #5
    scan_kernel<<<NUM_TILES, THREADS>>>(feature, bank, cluL, clsL, cid, gtl); // #6
    gather_kernel<<<BQ, 64>>>(bank, (float*)d_out);         // #7
}

// round 10
// speedup vs baseline: 1.1429x; 1.1429x over previous
#include <cuda_runtime.h>
#include <cuda_bf16.h>

#define BQ 256
#define DD 256
#define NBANK 100000
#define NPAD 100096
#define TN 128
#define NUM_TILES ((NBANK + TN - 1) / TN)      // 782
#define NCH 8
#define KCH 32
#define SR 80                                   // smem row stride (64B data + 16B pad)
#define THREADS 256

typedef unsigned long long ull;
typedef unsigned int u32;

// --------------- device scratch --------------------------------------------
__device__ ull    g_aP[BQ];                     // approx masked min (primary)
__device__ ull    g_aF[BQ];                     // approx masked min (fallback)
__device__ ull    g_ex[BQ];                     // exact rescored min
__device__ float  g_a2[BQ];
__device__ int    g_b2maxI;
__device__ uint4  g_Q[NCH][BQ][4];              // hi-split queries
__device__ uint4  g_bankH[(size_t)NPAD * 32];   // bf16 hi bank image
__device__ float  g_b2[NPAD];
__device__ ull    g_tileP[(size_t)NUM_TILES * BQ];   // per-(tile,q) masked minima
__device__ ull    g_tileF[(size_t)NUM_TILES * BQ];

// --------------- smem layout (phase A) --------------------------------------
#define QBUF  (BQ * SR)                     // 20480
#define BBUF  (TN * SR)                     // 10240
#define OFF_Q    0
#define OFF_B    (2 * QBUF)                 // 40960
#define OFF_RED  (OFF_B + 2 * BBUF)         // 61440
#define OFF_B2S  (OFF_RED + 2 * BQ * 8)     // 65536
#define OFF_SCLU (OFF_B2S + 512)
#define OFF_SCLS (OFF_SCLU + 512)
#define OFF_SCID (OFF_SCLS + 512)
#define OFF_SGT  (OFF_SCID + 1024)
#define SMEM_TOTAL (OFF_SGT + 1024)         // 69120

// --------------- helpers -----------------------------------------------------
__device__ __forceinline__ u32 smem_u32(const void* p) {
    u32 a;
    asm("{ .reg .u64 t; cvta.to.shared.u64 t, %1; cvt.u32.u64 %0, t; }" : "=r"(a) : "l"(p));
    return a;
}
#define LDSM_X4(r, addr) \
    asm volatile("ldmatrix.sync.aligned.m8n8.x4.shared.b16 {%0,%1,%2,%3}, [%4];" \
        : "=r"((r)[0]), "=r"((r)[1]), "=r"((r)[2]), "=r"((r)[3]) : "r"(addr))
#define MMA16816(d, a, b0, b1) \
    asm volatile("mma.sync.aligned.m16n8k16.row.col.f32.bf16.bf16.f32 " \
        "{%0,%1,%2,%3}, {%4,%5,%6,%7}, {%8,%9}, {%0,%1,%2,%3};" \
        : "+f"((d)[0]), "+f"((d)[1]), "+f"((d)[2]), "+f"((d)[3]) \
        : "r"((a)[0]), "r"((a)[1]), "r"((a)[2]), "r"((a)[3]), "r"(b0), "r"(b1))
#define CP_ASYNC16(dst, src) \
    asm volatile("cp.async.cg.shared.global [%0], [%1], 16;" :: "r"(dst), "l"(src) : "memory")
#define CP_COMMIT() asm volatile("cp.async.commit_group;" ::: "memory")
#define CP_WAIT0()  asm volatile("cp.async.wait_group 0;" ::: "memory")

__device__ __forceinline__ ull encode(float f, int n) {
    u32 u = __float_as_uint(f);
    u = (u & 0x80000000u) ? ~u : (u | 0x80000000u);
    return ((ull)u << 32) | (u32)n;
}
__device__ __forceinline__ float decode_hi(ull e) {
    u32 u = (u32)(e >> 32);
    u = (u & 0x80000000u) ? (u ^ 0x80000000u) : ~u;
    return __uint_as_float(u);
}
__device__ __forceinline__ u32 hi2(float a0, float a1) {
    __nv_bfloat16 h0 = __float2bfloat16(a0);
    __nv_bfloat16 h1 = __float2bfloat16(a1);
    return (u32)__bfloat16_as_ushort(h0) | ((u32)__bfloat16_as_ushort(h1) << 16);
}

// ---------------------------------------------------------------------------
// prep: block c splits chunk c of all queries; block 0 also a2 + init minima.
// ---------------------------------------------------------------------------
__global__ void prep_kernel(const float* __restrict__ feat) {
    int c = blockIdx.x, q = threadIdx.x;
    const float* row = feat + q * DD;
    if (c == 0) {
        g_aP[q] = ~0ULL;
        g_aF[q] = ~0ULL;
        float s = 0.f;
        for (int k = 0; k < DD; ++k) s = fmaf(row[k], row[k], s);
        g_a2[q] = s;
        if (q == 0) g_b2maxI = 0;
    }
#pragma unroll
    for (int i = 0; i < 4; ++i) {
        u32 H[4];
#pragma unroll
        for (int e = 0; e < 8; e += 2) {
            int k = c * KCH + i * 8 + e;
            H[e >> 1] = hi2(row[k], row[k + 1]);
        }
        g_Q[c][q][i] = make_uint4(H[0], H[1], H[2], H[3]);
    }
}

// ---------------------------------------------------------------------------
// convert: bank fp32 -> bf16 hi image + exact b2 + global b2max.
// ---------------------------------------------------------------------------
__global__ void __launch_bounds__(256) convert_kernel(const float* __restrict__ bank) {
    int row = blockIdx.x * 8 + (threadIdx.x >> 5);
    if (row >= NBANK) return;
    int lane = threadIdx.x & 31;
    const float4* src = (const float4*)(bank + (size_t)row * DD) + lane * 2;
    float4 v0 = src[0], v1 = src[1];
    float vv[8] = {v0.x, v0.y, v0.z, v0.w, v1.x, v1.y, v1.z, v1.w};
    u32 H[4];
    float s = 0.f;
#pragma unroll
    for (int e = 0; e < 8; e += 2) {
        s = fmaf(vv[e], vv[e], s);
        s = fmaf(vv[e + 1], vv[e + 1], s);
        H[e >> 1] = hi2(vv[e], vv[e + 1]);
    }
    g_bankH[(size_t)row * 32 + lane] = make_uint4(H[0], H[1], H[2], H[3]);
#pragma unroll
    for (int o = 16; o; o >>= 1) s += __shfl_xor_sync(0xffffffffu, s, o);
    if (lane == 0) {
        g_b2[row] = s;
        atomicMax(&g_b2maxI, __float_as_int(s));   // s > 0 -> int order valid
    }
}

// ---------------------------------------------------------------------------
__device__ __forceinline__ void stage_chunk(u32 smb, int buf, int c, int tid, int n0) {
#pragma unroll
    for (int p = 0; p < 4; ++p) {            // Q: 1024 16B pieces
        int idx = tid + THREADS * p;
        int row = idx >> 2, seg = idx & 3;
        CP_ASYNC16(smb + OFF_Q + (u32)buf * QBUF + (u32)row * SR + (u32)seg * 16,
                   &g_Q[c][row][seg]);
    }
#pragma unroll
    for (int p = 0; p < 2; ++p) {            // B: 512 pieces
        int idx = tid + THREADS * p;
        int rw = idx >> 2, seg = idx & 3;
        CP_ASYNC16(smb + OFF_B + (u32)buf * BBUF + (u32)rw * SR + (u32)seg * 16,
                   g_bankH + (size_t)(n0 + rw) * 32 + c * 4 + seg);
    }
}

// ---------------------------------------------------------------------------
// Phase A: hi-only bf16 HMMA GEMM; per-(tile,q) masked minima + global approx.
// ---------------------------------------------------------------------------
__global__ void __launch_bounds__(THREADS, 1) main_kernel(
    const int* __restrict__ cluL, const int* __restrict__ clsL,
    const int* __restrict__ cid,  const int* __restrict__ gt)
{
    extern __shared__ char sm[];
    const u32 smb  = smem_u32(sm);
    const int tid  = threadIdx.x;
    const int lane = tid & 31;
    const int w    = tid >> 5;
    const int n0   = blockIdx.x * TN;

    ull*   redP = (ull*)(sm + OFF_RED);
    ull*   redF = redP + BQ;
    float* b2s  = (float*)(sm + OFF_B2S);
    int*   sClu = (int*)(sm + OFF_SCLU);
    int*   sCls = (int*)(sm + OFF_SCLS);
    int*   sCid = (int*)(sm + OFF_SCID);
    int*   sGt  = (int*)(sm + OFF_SGT);

    stage_chunk(smb, 0, 0, tid, n0);
    CP_COMMIT();

    redP[tid] = ~0ULL;
    redF[tid] = ~0ULL;
    sCid[tid] = cid[tid];
    sGt[tid]  = gt[tid];
    if (tid < TN) {
        int n = n0 + tid;
        bool v = (n < NBANK);
        sClu[tid] = v ? cluL[n] : -1;
        sCls[tid] = v ? clsL[n] : 0x7fffffff;
        b2s[tid]  = v ? g_b2[n] : 0.f;
    }

    const int q0 = (w & 3) * 64;
    const int nh = (w >> 2) * 64;

    float acc[4][8][4];
#pragma unroll
    for (int mi = 0; mi < 4; mi++)
#pragma unroll
        for (int nt = 0; nt < 8; nt++)
#pragma unroll
            for (int r = 0; r < 4; r++) acc[mi][nt][r] = 0.f;

    const u32 aRowOff = (u32)(q0 + (lane & 15)) * SR + (u32)(lane >> 4) * 16;
    const int bRow    = nh + ((lane >> 4) & 1) * 8 + (lane & 7);
    const u32 bColB   = ((lane >> 3) & 1) * 16;

#pragma unroll 1
    for (int c = 0; c < NCH; ++c) {
        CP_WAIT0();
        __syncthreads();
        if (c + 1 < NCH) { stage_chunk(smb, (c + 1) & 1, c + 1, tid, n0); CP_COMMIT(); }

        const int buf = c & 1;
        const u32 qH = smb + OFF_Q + (u32)buf * QBUF + aRowOff;
        const u32 bH = smb + OFF_B + (u32)buf * BBUF;
#pragma unroll
        for (int kk = 0; kk < KCH; kk += 16) {
            const u32 kb = (u32)kk * 2 + bColB;
            u32 aH[4][4];
#pragma unroll
            for (int mi = 0; mi < 4; mi++) LDSM_X4(aH[mi], qH + mi * 16 * SR + kk * 2);
            u32 bB[16];
#pragma unroll
            for (int p = 0; p < 4; p++)
                LDSM_X4(&bB[4 * p], bH + (u32)(bRow + p * 16) * SR + kb);
#pragma unroll
            for (int mi = 0; mi < 4; mi++)
#pragma unroll
                for (int nt = 0; nt < 8; nt++)
                    MMA16816(acc[mi][nt], aH[mi], bB[2 * nt], bB[2 * nt + 1]);
        }
    }

    // ---- epilogue: masked dual argmin from HMMA fragments ----
    {
        const int jb = nh + 2 * (lane & 3);
        float b2r[16]; int clsr[16], clur[16]; bool val[16];
#pragma unroll
        for (int ni = 0; ni < 8; ni++)
#pragma unroll
            for (int h = 0; h < 2; h++) {
                int j = jb + 8 * ni + h, x = ni * 2 + h;
                b2r[x]  = b2s[j];
                clsr[x] = sCls[j];
                clur[x] = sClu[j];
                val[x]  = (n0 + j) < NBANK;
            }
#pragma unroll
        for (int mi = 0; mi < 4; mi++) {
#pragma unroll
            for (int half = 0; half < 2; half++) {
                int r = q0 + mi * 16 + (lane >> 2) + 8 * half;
                int gtq = sGt[r], ciq = sCid[r];
                ull bp = ~0ULL, bf = ~0ULL;
#pragma unroll
                for (int ni = 0; ni < 8; ni++)
#pragma unroll
                    for (int h = 0; h < 2; h++) {
                        int x = ni * 2 + h;
                        if (!val[x] || clsr[x] == gtq) continue;
                        float score = fmaf(-2.f, acc[mi][ni][half * 2 + h], b2r[x]);
                        ull e = encode(score, n0 + jb + 8 * ni + h);
                        if (e < bf) bf = e;
                        if (clur[x] == ciq && e < bp) bp = e;
                    }
#pragma unroll
                for (int o = 1; o <= 2; o <<= 1) {
                    ull tp = __shfl_xor_sync(0xffffffffu, bp, o);
                    ull tf = __shfl_xor_sync(0xffffffffu, bf, o);
                    if (tp < bp) bp = tp;
                    if (tf < bf) bf = tf;
                }
                if ((lane & 3) == 0) {
                    if (bp != ~0ULL) atomicMin(&redP[r], bp);
                    if (bf != ~0ULL) atomicMin(&redF[r], bf);
                }
            }
        }
    }
    __syncthreads();
    {
        ull p = redP[tid], f = redF[tid];
        g_tileP[(size_t)blockIdx.x * BQ + tid] = p;     // coalesced 8B stores
        g_tileF[(size_t)blockIdx.x * BQ + tid] = f;
        if (p != ~0ULL) atomicMin(&g_aP[tid], p);
        if (f != ~0ULL) atomicMin(&g_aF[tid], f);
    }
}

// ---------------------------------------------------------------------------
// Phase B: one block per query. Pick tiles whose masked approx min is under
// the certified threshold, rescore those tiles' masked rows exactly in fp32.
// ---------------------------------------------------------------------------
__global__ void __launch_bounds__(256) rescore_kernel(
    const float* __restrict__ feat, const float* __restrict__ bank,
    const int* __restrict__ cluL, const int* __restrict__ clsL,
    const int* __restrict__ cid,  const int* __restrict__ gt)
{
    __shared__ int   s_tiles[NUM_TILES];
    __shared__ int   s_cnt;
    __shared__ ull   s_best;
    __shared__ float s_thr;
    __shared__ int   s_hasP, s_gt, s_cid;

    const int q    = blockIdx.x;
    const int tid  = threadIdx.x;
    const int lane = tid & 31;
    const int w    = tid >> 5;

    if (tid == 0) {
        s_cnt  = 0;
        s_best = ~0ULL;
        bool hasP = (g_aP[q] != ~0ULL);
        float amin = hasP ? decode_hi(g_aP[q]) : decode_hi(g_aF[q]);
        float m = 0.0078125f * 1.05f * sqrtf(g_a2[q] * __int_as_float(g_b2maxI)) + 0.02f;
        s_thr  = amin + 2.f * m;
        s_hasP = hasP ? 1 : 0;
        s_gt   = gt[q];
        s_cid  = cid[q];
    }
    __syncthreads();

    for (int t = tid; t < NUM_TILES; t += 256) {
        ull tm = s_hasP ? g_tileP[(size_t)t * BQ + q] : g_tileF[(size_t)t * BQ + q];
        if (tm != ~0ULL && decode_hi(tm) <= s_thr) {
            int i = atomicAdd(&s_cnt, 1);
            s_tiles[i] = t;
        }
    }
    __syncthreads();

    const int cnt = s_cnt;
    const float4* fa = (const float4*)(feat + (size_t)q * DD);
    const float4 qa0 = fa[lane * 2], qa1 = fa[lane * 2 + 1];

    for (int i = 0; i < cnt; ++i) {
        const int n0 = s_tiles[i] * TN;
#pragma unroll 1
        for (int r = w; r < TN; r += 8) {                 // warp per row
            int n = n0 + r;
            if (n >= NBANK) continue;
            if (clsL[n] == s_gt) continue;
            if (s_hasP && cluL[n] != s_cid) continue;
            const float4* fb = (const float4*)(bank + (size_t)n * DD);
            float4 b0 = fb[lane * 2], b1 = fb[lane * 2 + 1];
            float d = 0.f;
            d = fmaf(qa0.x, b0.x, d); d = fmaf(qa0.y, b0.y, d);
            d = fmaf(qa0.z, b0.z, d); d = fmaf(qa0.w, b0.w, d);
            d = fmaf(qa1.x, b1.x, d); d = fmaf(qa1.y, b1.y, d);
            d = fmaf(qa1.z, b1.z, d); d = fmaf(qa1.w, b1.w, d);
#pragma unroll
            for (int o = 16; o; o >>= 1) d += __shfl_xor_sync(0xffffffffu, d, o);
            if (lane == 0)
                atomicMin(&s_best, encode(fmaf(-2.f, d, g_b2[n]), n));
        }
    }
    __syncthreads();
    if (tid == 0) g_ex[q] = s_best;
}

// ---------------------------------------------------------------------------
__global__ void gather_kernel(const float* __restrict__ bank, float* __restrict__ out) {
    int b = blockIdx.x;
    ull e = g_ex[b];
    int idx = (e == ~0ULL) ? 0 : (int)(u32)(e & 0xffffffffu);
    const float4* src = (const float4*)(bank + (size_t)idx * DD);
    float4*       dst = (float4*)(out + (size_t)b * DD);
    dst[threadIdx.x] = src[threadIdx.x];
}

__global__ void noop_kernel() {}   // keeps main_kernel at launch #4 for ncu

// ---------------------------------------------------------------------------
extern "C" void kernel_launch(void* const* d_in, const int* in_sizes, int n_in,
                              void* d_out, int out_size) {
    const float* feature = (const float*)d_in[0];
    const float* bank    = (const float*)d_in[1];
    const int*   cluL    = (const int*)d_in[2];
    const int*   clsL    = (const int*)d_in[3];
    const int*   cid     = (const int*)d_in[4];
    const int*   gtl     = (const int*)d_in[5];

    cudaFuncSetAttribute(main_kernel,
                         cudaFuncAttributeMaxDynamicSharedMemorySize, SMEM_TOTAL);

    prep_kernel<<<NCH, BQ>>>(feature);                      // #1
    convert_kernel<<<(NBANK + 7) / 8, 256>>>(bank);         // #2
    noop_kernel<<<1, 32>>>();                               // #3
    main_kernel<<<NUM_TILES, THREADS, SMEM_TOTAL>>>(cluL, clsL, cid, gtl);  // #4 (ncu)
    rescore_kernel<<<BQ, 256>>>(feature, bank, cluL, clsL, cid, gtl);       // #5
    gather_kernel<<<BQ, 64>>>(bank, (float*)d_out);         // #6
}

// round 11
// speedup vs baseline: 1.3692x; 1.1981x over previous
#include <cuda_runtime.h>
#include <cuda_bf16.h>

#define BQ 256
#define DD 256
#define NBANK 100000
#define TN 128
#define NUM_TILES ((NBANK + TN - 1) / TN)      // 782
#define NCH 8
#define KCH 32
#define SR 80                                   // Q smem row stride (64B data + 16B pad)
#define SB 528                                  // B smem row stride (512B data + 16B pad)
#define THREADS 256

typedef unsigned long long ull;
typedef unsigned int u32;

// --------------- device scratch --------------------------------------------
__device__ ull    g_aP[BQ];                     // approx masked min (primary)
__device__ ull    g_aF[BQ];                     // approx masked min (fallback)
__device__ ull    g_ex[BQ];                     // exact rescored min
__device__ float  g_a2[BQ];
__device__ int    g_b2maxI;
__device__ uint4  g_Q[NCH][BQ][4];              // hi-split queries (L2-resident)
__device__ float  g_b2[NBANK];
__device__ ull    g_tileP[(size_t)NUM_TILES * BQ];
__device__ ull    g_tileF[(size_t)NUM_TILES * BQ];

// --------------- smem layout (phase A) --------------------------------------
#define QBUF  (BQ * SR)                     // 20480
#define OFF_Q    0                          // [2 buf][256][SR]
#define OFF_B    (2 * QBUF)                 // 40960: full-K bf16 tile [128][SB]
#define OFF_RED  (OFF_B + TN * SB)          // 108544
#define OFF_B2S  (OFF_RED + 2 * BQ * 8)     // 112640
#define OFF_SCLU (OFF_B2S + 512)
#define OFF_SCLS (OFF_SCLU + 512)
#define OFF_SCID (OFF_SCLS + 512)
#define OFF_SGT  (OFF_SCID + 1024)
#define SMEM_TOTAL (OFF_SGT + 1024)         // 116224

// --------------- helpers -----------------------------------------------------
__device__ __forceinline__ u32 smem_u32(const void* p) {
    u32 a;
    asm("{ .reg .u64 t; cvta.to.shared.u64 t, %1; cvt.u32.u64 %0, t; }" : "=r"(a) : "l"(p));
    return a;
}
#define LDSM_X4(r, addr) \
    asm volatile("ldmatrix.sync.aligned.m8n8.x4.shared.b16 {%0,%1,%2,%3}, [%4];" \
        : "=r"((r)[0]), "=r"((r)[1]), "=r"((r)[2]), "=r"((r)[3]) : "r"(addr))
#define MMA16816(d, a, b0, b1) \
    asm volatile("mma.sync.aligned.m16n8k16.row.col.f32.bf16.bf16.f32 " \
        "{%0,%1,%2,%3}, {%4,%5,%6,%7}, {%8,%9}, {%0,%1,%2,%3};" \
        : "+f"((d)[0]), "+f"((d)[1]), "+f"((d)[2]), "+f"((d)[3]) \
        : "r"((a)[0]), "r"((a)[1]), "r"((a)[2]), "r"((a)[3]), "r"(b0), "r"(b1))
#define CP_ASYNC16(dst, src) \
    asm volatile("cp.async.cg.shared.global [%0], [%1], 16;" :: "r"(dst), "l"(src) : "memory")
#define CP_COMMIT() asm volatile("cp.async.commit_group;" ::: "memory")
#define CP_WAIT0()  asm volatile("cp.async.wait_group 0;" ::: "memory")

__device__ __forceinline__ ull encode(float f, int n) {
    u32 u = __float_as_uint(f);
    u = (u & 0x80000000u) ? ~u : (u | 0x80000000u);
    return ((ull)u << 32) | (u32)n;
}
__device__ __forceinline__ float decode_hi(ull e) {
    u32 u = (u32)(e >> 32);
    u = (u & 0x80000000u) ? (u ^ 0x80000000u) : ~u;
    return __uint_as_float(u);
}
__device__ __forceinline__ u32 hi2(float a0, float a1) {
    __nv_bfloat16 h0 = __float2bfloat16(a0);
    __nv_bfloat16 h1 = __float2bfloat16(a1);
    return (u32)__bfloat16_as_ushort(h0) | ((u32)__bfloat16_as_ushort(h1) << 16);
}

// ---------------------------------------------------------------------------
// prep: block c splits chunk c of all queries; block 0 also a2 + inits.
// ---------------------------------------------------------------------------
__global__ void prep_kernel(const float* __restrict__ feat) {
    int c = blockIdx.x, q = threadIdx.x;
    const float* row = feat + q * DD;
    if (c == 0) {
        g_aP[q] = ~0ULL;
        g_aF[q] = ~0ULL;
        float s = 0.f;
        for (int k = 0; k < DD; ++k) s = fmaf(row[k], row[k], s);
        g_a2[q] = s;
        if (q == 0) g_b2maxI = 0;
    }
#pragma unroll
    for (int i = 0; i < 4; ++i) {
        u32 H[4];
#pragma unroll
        for (int e = 0; e < 8; e += 2) {
            int k = c * KCH + i * 8 + e;
            H[e >> 1] = hi2(row[k], row[k + 1]);
        }
        g_Q[c][q][i] = make_uint4(H[0], H[1], H[2], H[3]);
    }
}

// ---------------------------------------------------------------------------
__device__ __forceinline__ void stage_q(u32 smb, int buf, int c, int tid) {
#pragma unroll
    for (int p = 0; p < 4; ++p) {            // 1024 16B pieces / 256 threads
        int idx = tid + THREADS * p;
        int row = idx >> 2, seg = idx & 3;
        CP_ASYNC16(smb + OFF_Q + (u32)buf * QBUF + (u32)row * SR + (u32)seg * 16,
                   &g_Q[c][row][seg]);
    }
}

// ---------------------------------------------------------------------------
// Phase A (fused): fp32 bank tile -> bf16 smem + exact b2 (to gmem), hi-only
// HMMA GEMM vs 256 queries, per-(tile,q) masked minima + global approx mins.
// ---------------------------------------------------------------------------
__global__ void __launch_bounds__(THREADS, 1) main_kernel(
    const float* __restrict__ bank,
    const int* __restrict__ cluL, const int* __restrict__ clsL,
    const int* __restrict__ cid,  const int* __restrict__ gt)
{
    extern __shared__ char sm[];
    const u32 smb  = smem_u32(sm);
    const int tid  = threadIdx.x;
    const int lane = tid & 31;
    const int w    = tid >> 5;
    const int n0   = blockIdx.x * TN;

    ull*   redP = (ull*)(sm + OFF_RED);
    ull*   redF = redP + BQ;
    float* b2s  = (float*)(sm + OFF_B2S);
    int*   sClu = (int*)(sm + OFF_SCLU);
    int*   sCls = (int*)(sm + OFF_SCLS);
    int*   sCid = (int*)(sm + OFF_SCID);
    int*   sGt  = (int*)(sm + OFF_SGT);

    stage_q(smb, 0, 0, tid);
    CP_COMMIT();

    redP[tid] = ~0ULL;
    redF[tid] = ~0ULL;
    sCid[tid] = cid[tid];
    sGt[tid]  = gt[tid];
    if (tid < TN) {
        int n = n0 + tid;
        bool v = (n < NBANK);
        sClu[tid] = v ? cluL[n] : -1;
        sCls[tid] = v ? clsL[n] : 0x7fffffff;
    }

    // ---- fused convert: warp w handles rows [16w, 16w+16) ----
    {
        const float4* bsrc = (const float4*)bank;
#pragma unroll 1
        for (int it = 0; it < 16; ++it) {
            int row = w * 16 + it;
            int gn  = n0 + row;
            float s = 0.f;
#pragma unroll
            for (int half = 0; half < 2; ++half) {
                float4 v = make_float4(0.f, 0.f, 0.f, 0.f);
                if (gn < NBANK) v = bsrc[(size_t)gn * 64 + half * 32 + lane];
                s = fmaf(v.x, v.x, s); s = fmaf(v.y, v.y, s);
                s = fmaf(v.z, v.z, s); s = fmaf(v.w, v.w, s);
                *(uint2*)(sm + OFF_B + row * SB + half * 256 + lane * 8) =
                    make_uint2(hi2(v.x, v.y), hi2(v.z, v.w));
            }
#pragma unroll
            for (int o = 16; o; o >>= 1) s += __shfl_xor_sync(0xffffffffu, s, o);
            if (lane == 0) {
                b2s[row] = s;
                if (gn < NBANK) {
                    g_b2[gn] = s;
                    atomicMax(&g_b2maxI, __float_as_int(s));   // s>0 -> int order ok
                }
            }
        }
    }

    const int q0 = (w & 3) * 64;
    const int nh = (w >> 2) * 64;

    float acc[4][8][4];
#pragma unroll
    for (int mi = 0; mi < 4; mi++)
#pragma unroll
        for (int nt = 0; nt < 8; nt++)
#pragma unroll
            for (int r = 0; r < 4; r++) acc[mi][nt][r] = 0.f;

    const u32 aRowOff = (u32)(q0 + (lane & 15)) * SR + (u32)(lane >> 4) * 16;
    const int bRow    = nh + ((lane >> 4) & 1) * 8 + (lane & 7);
    const u32 bColB   = ((lane >> 3) & 1) * 16;
    const u32 bBase   = smb + OFF_B;

#pragma unroll 1
    for (int c = 0; c < NCH; ++c) {
        CP_WAIT0();
        __syncthreads();                      // Q chunk c resident (+B tile for c=0)
        if (c + 1 < NCH) { stage_q(smb, (c + 1) & 1, c + 1, tid); CP_COMMIT(); }

        const u32 qH = smb + OFF_Q + (u32)(c & 1) * QBUF + aRowOff;
#pragma unroll
        for (int kk = 0; kk < KCH; kk += 16) {
            const u32 kb = (u32)(c * KCH + kk) * 2 + bColB;
            u32 aH[4][4];
#pragma unroll
            for (int mi = 0; mi < 4; mi++) LDSM_X4(aH[mi], qH + mi * 16 * SR + kk * 2);
            u32 bB[16];
#pragma unroll
            for (int p = 0; p < 4; p++)
                LDSM_X4(&bB[4 * p], bBase + (u32)(bRow + p * 16) * SB + kb);
#pragma unroll
            for (int mi = 0; mi < 4; mi++)
#pragma unroll
                for (int nt = 0; nt < 8; nt++)
                    MMA16816(acc[mi][nt], aH[mi], bB[2 * nt], bB[2 * nt + 1]);
        }
    }

    // ---- epilogue: masked dual argmin from HMMA fragments ----
    {
        const int jb = nh + 2 * (lane & 3);
        float b2r[16]; int clsr[16], clur[16]; bool val[16];
#pragma unroll
        for (int ni = 0; ni < 8; ni++)
#pragma unroll
            for (int h = 0; h < 2; h++) {
                int j = jb + 8 * ni + h, x = ni * 2 + h;
                b2r[x]  = b2s[j];
                clsr[x] = sCls[j];
                clur[x] = sClu[j];
                val[x]  = (n0 + j) < NBANK;
            }
#pragma unroll
        for (int mi = 0; mi < 4; mi++) {
#pragma unroll
            for (int half = 0; half < 2; half++) {
                int r = q0 + mi * 16 + (lane >> 2) + 8 * half;
                int gtq = sGt[r], ciq = sCid[r];
                ull bp = ~0ULL, bf = ~0ULL;
#pragma unroll
                for (int ni = 0; ni < 8; ni++)
#pragma unroll
                    for (int h = 0; h < 2; h++) {
                        int x = ni * 2 + h;
                        if (!val[x] || clsr[x] == gtq) continue;
                        float score = fmaf(-2.f, acc[mi][ni][half * 2 + h], b2r[x]);
                        ull e = encode(score, n0 + jb + 8 * ni + h);
                        if (e < bf) bf = e;
                        if (clur[x] == ciq && e < bp) bp = e;
                    }
#pragma unroll
                for (int o = 1; o <= 2; o <<= 1) {
                    ull tp = __shfl_xor_sync(0xffffffffu, bp, o);
                    ull tf = __shfl_xor_sync(0xffffffffu, bf, o);
                    if (tp < bp) bp = tp;
                    if (tf < bf) bf = tf;
                }
                if ((lane & 3) == 0) {
                    if (bp != ~0ULL) atomicMin(&redP[r], bp);
                    if (bf != ~0ULL) atomicMin(&redF[r], bf);
                }
            }
        }
    }
    __syncthreads();
    {
        ull p = redP[tid], f = redF[tid];
        g_tileP[(size_t)blockIdx.x * BQ + tid] = p;
        g_tileF[(size_t)blockIdx.x * BQ + tid] = f;
        if (p != ~0ULL) atomicMin(&g_aP[tid], p);
        if (f != ~0ULL) atomicMin(&g_aF[tid], f);
    }
}

// ---------------------------------------------------------------------------
// Phase B: one block (512 thr) per query; certified tile selection + exact
// fp32 rescore of qualifying tiles' masked rows.
// ---------------------------------------------------------------------------
__global__ void __launch_bounds__(512) rescore_kernel(
    const float* __restrict__ feat, const float* __restrict__ bank,
    const int* __restrict__ cluL, const int* __restrict__ clsL,
    const int* __restrict__ cid,  const int* __restrict__ gt)
{
    __shared__ int   s_tiles[NUM_TILES];
    __shared__ int   s_cnt;
    __shared__ ull   s_best;
    __shared__ float s_thr;
    __shared__ int   s_hasP, s_gt, s_cid;

    const int q    = blockIdx.x;
    const int tid  = threadIdx.x;
    const int lane = tid & 31;
    const int w    = tid >> 5;

    if (tid == 0) {
        s_cnt  = 0;
        s_best = ~0ULL;
        bool hasP = (g_aP[q] != ~0ULL);
        float amin = hasP ? decode_hi(g_aP[q]) : decode_hi(g_aF[q]);
        float m = 0.0078125f * 1.05f * sqrtf(g_a2[q] * __int_as_float(g_b2maxI)) + 0.02f;
        s_thr  = amin + 2.f * m;
        s_hasP = hasP ? 1 : 0;
        s_gt   = gt[q];
        s_cid  = cid[q];
    }
    __syncthreads();

    for (int t = tid; t < NUM_TILES; t += 512) {
        ull tm = s_hasP ? g_tileP[(size_t)t * BQ + q] : g_tileF[(size_t)t * BQ + q];
        if (tm != ~0ULL && decode_hi(tm) <= s_thr) {
            int i = atomicAdd(&s_cnt, 1);
            s_tiles[i] = t;
        }
    }
    __syncthreads();

    const int cnt = s_cnt;
    const float4* fa = (const float4*)(feat + (size_t)q * DD);
    const float4 qa0 = fa[lane * 2], qa1 = fa[lane * 2 + 1];

    for (int i = 0; i < cnt; ++i) {
        const int n0 = s_tiles[i] * TN;
#pragma unroll 1
        for (int r = w; r < TN; r += 16) {               // warp per row, 16 warps
            int n = n0 + r;
            if (n >= NBANK) continue;
            if (clsL[n] == s_gt) continue;
            if (s_hasP && cluL[n] != s_cid) continue;
            const float4* fb = (const float4*)(bank + (size_t)n * DD);
            float4 b0 = fb[lane * 2], b1 = fb[lane * 2 + 1];
            float d = 0.f;
            d = fmaf(qa0.x, b0.x, d); d = fmaf(qa0.y, b0.y, d);
            d = fmaf(qa0.z, b0.z, d); d = fmaf(qa0.w, b0.w, d);
            d = fmaf(qa1.x, b1.x, d); d = fmaf(qa1.y, b1.y, d);
            d = fmaf(qa1.z, b1.z, d); d = fmaf(qa1.w, b1.w, d);
#pragma unroll
            for (int o = 16; o; o >>= 1) d += __shfl_xor_sync(0xffffffffu, d, o);
            if (lane == 0)
                atomicMin(&s_best, encode(fmaf(-2.f, d, g_b2[n]), n));
        }
    }
    __syncthreads();
    if (tid == 0) g_ex[q] = s_best;
}

// ---------------------------------------------------------------------------
__global__ void gather_kernel(const float* __restrict__ bank, float* __restrict__ out) {
    int b = blockIdx.x;
    ull e = g_ex[b];
    int idx = (e == ~0ULL) ? 0 : (int)(u32)(e & 0xffffffffu);
    const float4* src = (const float4*)(bank + (size_t)idx * DD);
    float4*       dst = (float4*)(out + (size_t)b * DD);
    dst[threadIdx.x] = src[threadIdx.x];
}

__global__ void noop_kernel() {}   // launch #4 = rescore_kernel -> ncu profiles it

// ---------------------------------------------------------------------------
extern "C" void kernel_launch(void* const* d_in, const int* in_sizes, int n_in,
                              void* d_out, int out_size) {
    const float* feature = (const float*)d_in[0];
    const float* bank    = (const float*)d_in[1];
    const int*   cluL    = (const int*)d_in[2];
    const int*   clsL    = (const int*)d_in[3];
    const int*   cid     = (const int*)d_in[4];
    const int*   gtl     = (const int*)d_in[5];

    cudaFuncSetAttribute(main_kernel,
                         cudaFuncAttributeMaxDynamicSharedMemorySize, SMEM_TOTAL);

    prep_kernel<<<NCH, BQ>>>(feature);                                        // #1
    main_kernel<<<NUM_TILES, THREADS, SMEM_TOTAL>>>(bank, cluL, clsL, cid, gtl); // #2
    noop_kernel<<<1, 32>>>();                                                 // #3
    rescore_kernel<<<BQ, 512>>>(feature, bank, cluL, clsL, cid, gtl);         // #4 (ncu)
    gather_kernel<<<BQ, 64>>>(bank, (float*)d_out);                           // #5
}

// round 12
// speedup vs baseline: 1.6180x; 1.1817x over previous
#include <cuda_runtime.h>
#include <cuda_bf16.h>

#define BQ 256
#define DD 256
#define NBANK 100000
#define TN 128
#define NUM_TILES ((NBANK + TN - 1) / TN)      // 782
#define NCH 8
#define KCH 32
#define SR 80                                   // smem row stride (64B data + 16B pad)
#define THREADS 256

typedef unsigned long long ull;
typedef unsigned int u32;

// --------------- device scratch --------------------------------------------
__device__ ull    g_aP[BQ];
__device__ ull    g_aF[BQ];
__device__ float  g_a2[BQ];
__device__ int    g_b2maxI;
__device__ uint4  g_Q[NCH][BQ][4];              // hi-split queries (L2-resident)
__device__ float  g_b2[NBANK];
__device__ ull    g_tileP[(size_t)BQ * NUM_TILES];   // [q][tile] (coalesced reads)
__device__ ull    g_tileF[(size_t)BQ * NUM_TILES];

// --------------- smem layout -------------------------------------------------
#define QBUF  (BQ * SR)                     // 20480
#define BBUF  (TN * SR)                     // 10240
#define OFF_Q    0                          // [2 buf][256][SR]
#define OFF_B    (2 * QBUF)                 // 40960: [2 buf][128][SR]
#define OFF_RED  (OFF_B + 2 * BBUF)         // 61440
#define OFF_B2S  (OFF_RED + 2 * BQ * 8)     // 65536
#define OFF_SCLU (OFF_B2S + 512)
#define OFF_SCLS (OFF_SCLU + 512)
#define OFF_SCID (OFF_SCLS + 512)
#define OFF_SGT  (OFF_SCID + 1024)
#define SMEM_TOTAL (OFF_SGT + 1024)         // 69120

// --------------- helpers -----------------------------------------------------
__device__ __forceinline__ u32 smem_u32(const void* p) {
    u32 a;
    asm("{ .reg .u64 t; cvta.to.shared.u64 t, %1; cvt.u32.u64 %0, t; }" : "=r"(a) : "l"(p));
    return a;
}
#define LDSM_X4(r, addr) \
    asm volatile("ldmatrix.sync.aligned.m8n8.x4.shared.b16 {%0,%1,%2,%3}, [%4];" \
        : "=r"((r)[0]), "=r"((r)[1]), "=r"((r)[2]), "=r"((r)[3]) : "r"(addr))
#define MMA16816(d, a, b0, b1) \
    asm volatile("mma.sync.aligned.m16n8k16.row.col.f32.bf16.bf16.f32 " \
        "{%0,%1,%2,%3}, {%4,%5,%6,%7}, {%8,%9}, {%0,%1,%2,%3};" \
        : "+f"((d)[0]), "+f"((d)[1]), "+f"((d)[2]), "+f"((d)[3]) \
        : "r"((a)[0]), "r"((a)[1]), "r"((a)[2]), "r"((a)[3]), "r"(b0), "r"(b1))
#define CP_ASYNC16(dst, src) \
    asm volatile("cp.async.cg.shared.global [%0], [%1], 16;" :: "r"(dst), "l"(src) : "memory")
#define CP_COMMIT() asm volatile("cp.async.commit_group;" ::: "memory")
#define CP_WAIT0()  asm volatile("cp.async.wait_group 0;" ::: "memory")

__device__ __forceinline__ ull encode(float f, int n) {
    u32 u = __float_as_uint(f);
    u = (u & 0x80000000u) ? ~u : (u | 0x80000000u);
    return ((ull)u << 32) | (u32)n;
}
__device__ __forceinline__ float decode_hi(ull e) {
    u32 u = (u32)(e >> 32);
    u = (u & 0x80000000u) ? (u ^ 0x80000000u) : ~u;
    return __uint_as_float(u);
}
__device__ __forceinline__ u32 hi2(float a0, float a1) {
    __nv_bfloat16 h0 = __float2bfloat16(a0);
    __nv_bfloat16 h1 = __float2bfloat16(a1);
    return (u32)__bfloat16_as_ushort(h0) | ((u32)__bfloat16_as_ushort(h1) << 16);
}

// ---------------------------------------------------------------------------
__global__ void prep_kernel(const float* __restrict__ feat) {
    int c = blockIdx.x, q = threadIdx.x;
    const float* row = feat + q * DD;
    if (c == 0) {
        g_aP[q] = ~0ULL;
        g_aF[q] = ~0ULL;
        float s = 0.f;
        for (int k = 0; k < DD; ++k) s = fmaf(row[k], row[k], s);
        g_a2[q] = s;
        if (q == 0) g_b2maxI = 0;
    }
#pragma unroll
    for (int i = 0; i < 4; ++i) {
        u32 H[4];
#pragma unroll
        for (int e = 0; e < 8; e += 2) {
            int k = c * KCH + i * 8 + e;
            H[e >> 1] = hi2(row[k], row[k + 1]);
        }
        g_Q[c][q][i] = make_uint4(H[0], H[1], H[2], H[3]);
    }
}

// ---------------------------------------------------------------------------
__device__ __forceinline__ void stage_q(u32 smb, int buf, int c, int tid) {
#pragma unroll
    for (int p = 0; p < 4; ++p) {
        int idx = tid + THREADS * p;
        int row = idx >> 2, seg = idx & 3;
        CP_ASYNC16(smb + OFF_Q + (u32)buf * QBUF + (u32)row * SR + (u32)seg * 16,
                   &g_Q[c][row][seg]);
    }
}

// Load 16 fp32 (one chunk-half of one bank row) into regs; zero for pad rows.
__device__ __forceinline__ void ldB(const float* __restrict__ bank, int gn, int c,
                                    int half, float4* r) {
    if (gn < NBANK) {
        const float4* p = (const float4*)(bank + (size_t)gn * DD + c * KCH + half * 16);
        r[0] = p[0]; r[1] = p[1]; r[2] = p[2]; r[3] = p[3];
    } else {
        r[0] = r[1] = r[2] = r[3] = make_float4(0.f, 0.f, 0.f, 0.f);
    }
}
// Convert 16 fp32 -> bf16 hi, store 32B to smem; return partial square-sum.
__device__ __forceinline__ float cvtB(const float4* r, char* dst) {
    float s = 0.f;
#pragma unroll
    for (int i = 0; i < 4; ++i) {
        s = fmaf(r[i].x, r[i].x, s); s = fmaf(r[i].y, r[i].y, s);
        s = fmaf(r[i].z, r[i].z, s); s = fmaf(r[i].w, r[i].w, s);
    }
    ((uint4*)dst)[0] = make_uint4(hi2(r[0].x, r[0].y), hi2(r[0].z, r[0].w),
                                  hi2(r[1].x, r[1].y), hi2(r[1].z, r[1].w));
    ((uint4*)dst)[1] = make_uint4(hi2(r[2].x, r[2].y), hi2(r[2].z, r[2].w),
                                  hi2(r[3].x, r[3].y), hi2(r[3].z, r[3].w));
    return s;
}

// ---------------------------------------------------------------------------
// Phase A: fused streaming convert + hi-only bf16 HMMA GEMM + masked dual
// argmin; per-(q,tile) minima out, exact b2 out.
// ---------------------------------------------------------------------------
__global__ void __launch_bounds__(THREADS, 1) main_kernel(
    const float* __restrict__ bank,
    const int* __restrict__ cluL, const int* __restrict__ clsL,
    const int* __restrict__ cid,  const int* __restrict__ gt)
{
    extern __shared__ char sm[];
    const u32 smb  = smem_u32(sm);
    const int tid  = threadIdx.x;
    const int lane = tid & 31;
    const int w    = tid >> 5;
    const int n0   = blockIdx.x * TN;

    ull*   redP = (ull*)(sm + OFF_RED);
    ull*   redF = redP + BQ;
    float* b2s  = (float*)(sm + OFF_B2S);
    int*   sClu = (int*)(sm + OFF_SCLU);
    int*   sCls = (int*)(sm + OFF_SCLS);
    int*   sCid = (int*)(sm + OFF_SCID);
    int*   sGt  = (int*)(sm + OFF_SGT);

    // conversion ownership: thread -> (row, half)
    const int crow  = tid >> 1;
    const int chalf = tid & 1;
    const int cgn   = n0 + crow;
    float b2part = 0.f;

    stage_q(smb, 0, 0, tid);
    CP_COMMIT();
    {   // convert B chunk 0 into buf 0
        float4 r[4];
        ldB(bank, cgn, 0, chalf, r);
        b2part += cvtB(r, sm + OFF_B + crow * SR + chalf * 32);
    }

    redP[tid] = ~0ULL;
    redF[tid] = ~0ULL;
    sCid[tid] = cid[tid];
    sGt[tid]  = gt[tid];
    if (tid < TN) {
        int n = n0 + tid;
        bool v = (n < NBANK);
        sClu[tid] = v ? cluL[n] : -1;
        sCls[tid] = v ? clsL[n] : 0x7fffffff;
    }

    const int q0 = (w & 3) * 64;
    const int nh = (w >> 2) * 64;

    float acc[4][8][4];
#pragma unroll
    for (int mi = 0; mi < 4; mi++)
#pragma unroll
        for (int nt = 0; nt < 8; nt++)
#pragma unroll
            for (int r = 0; r < 4; r++) acc[mi][nt][r] = 0.f;

    const u32 aRowOff = (u32)(q0 + (lane & 15)) * SR + (u32)(lane >> 4) * 16;
    const int bRow    = nh + ((lane >> 4) & 1) * 8 + (lane & 7);
    const u32 bColB   = ((lane >> 3) & 1) * 16;

    CP_WAIT0();
    __syncthreads();                          // chunk 0 (Q + B) resident

#pragma unroll 1
    for (int c = 0; c < NCH; ++c) {
        float4 pre[4];
        if (c + 1 < NCH) {
            ldB(bank, cgn, c + 1, chalf, pre);     // LDGs overlap MMAs below
            stage_q(smb, (c + 1) & 1, c + 1, tid);
            CP_COMMIT();
        }

        const u32 qH = smb + OFF_Q + (u32)(c & 1) * QBUF + aRowOff;
        const u32 bB0 = smb + OFF_B + (u32)(c & 1) * BBUF;
#pragma unroll
        for (int kk = 0; kk < KCH; kk += 16) {
            const u32 kb = (u32)kk * 2 + bColB;
            u32 aH[4][4];
#pragma unroll
            for (int mi = 0; mi < 4; mi++) LDSM_X4(aH[mi], qH + mi * 16 * SR + kk * 2);
            u32 bB[16];
#pragma unroll
            for (int p = 0; p < 4; p++)
                LDSM_X4(&bB[4 * p], bB0 + (u32)(bRow + p * 16) * SR + kb);
#pragma unroll
            for (int mi = 0; mi < 4; mi++)
#pragma unroll
                for (int nt = 0; nt < 8; nt++)
                    MMA16816(acc[mi][nt], aH[mi], bB[2 * nt], bB[2 * nt + 1]);
        }

        if (c + 1 < NCH)
            b2part += cvtB(pre, sm + OFF_B + ((c + 1) & 1) * BBUF + crow * SR + chalf * 32);

        CP_WAIT0();
        __syncthreads();
    }

    // finalize exact b2 per row (half0 + half1)
    {
        float other = __shfl_xor_sync(0xffffffffu, b2part, 1);
        if (chalf == 0) {
            float tot = b2part + other;
            b2s[crow] = tot;
            if (cgn < NBANK) {
                g_b2[cgn] = tot;
                atomicMax(&g_b2maxI, __float_as_int(tot));   // tot>0 -> int order ok
            }
        }
    }
    __syncthreads();

    // ---- epilogue: masked dual argmin from HMMA fragments ----
    {
        const int jb = nh + 2 * (lane & 3);
        float b2r[16]; int clsr[16], clur[16]; bool val[16];
#pragma unroll
        for (int ni = 0; ni < 8; ni++)
#pragma unroll
            for (int h = 0; h < 2; h++) {
                int j = jb + 8 * ni + h, x = ni * 2 + h;
                b2r[x]  = b2s[j];
                clsr[x] = sCls[j];
                clur[x] = sClu[j];
                val[x]  = (n0 + j) < NBANK;
            }
#pragma unroll
        for (int mi = 0; mi < 4; mi++) {
#pragma unroll
            for (int half = 0; half < 2; half++) {
                int r = q0 + mi * 16 + (lane >> 2) + 8 * half;
                int gtq = sGt[r], ciq = sCid[r];
                ull bp = ~0ULL, bf = ~0ULL;
#pragma unroll
                for (int ni = 0; ni < 8; ni++)
#pragma unroll
                    for (int h = 0; h < 2; h++) {
                        int x = ni * 2 + h;
                        if (!val[x] || clsr[x] == gtq) continue;
                        float score = fmaf(-2.f, acc[mi][ni][half * 2 + h], b2r[x]);
                        ull e = encode(score, n0 + jb + 8 * ni + h);
                        if (e < bf) bf = e;
                        if (clur[x] == ciq && e < bp) bp = e;
                    }
#pragma unroll
                for (int o = 1; o <= 2; o <<= 1) {
                    ull tp = __shfl_xor_sync(0xffffffffu, bp, o);
                    ull tf = __shfl_xor_sync(0xffffffffu, bf, o);
                    if (tp < bp) bp = tp;
                    if (tf < bf) bf = tf;
                }
                if ((lane & 3) == 0) {
                    if (bp != ~0ULL) atomicMin(&redP[r], bp);
                    if (bf != ~0ULL) atomicMin(&redF[r], bf);
                }
            }
        }
    }
    __syncthreads();
    {
        ull p = redP[tid], f = redF[tid];
        g_tileP[(size_t)tid * NUM_TILES + blockIdx.x] = p;   // [q][tile]
        g_tileF[(size_t)tid * NUM_TILES + blockIdx.x] = f;
        if (p != ~0ULL) atomicMin(&g_aP[tid], p);
        if (f != ~0ULL) atomicMin(&g_aF[tid], f);
    }
}

// ---------------------------------------------------------------------------
// Phase B (+gather): one block per query; certified tile pick, exact fp32
// rescore of qualifying rows, winner row written straight to output.
// ---------------------------------------------------------------------------
__global__ void __launch_bounds__(512) rescore_kernel(
    const float* __restrict__ feat, const float* __restrict__ bank,
    const int* __restrict__ cluL, const int* __restrict__ clsL,
    const int* __restrict__ cid,  const int* __restrict__ gt,
    float* __restrict__ out)
{
    __shared__ int   s_tiles[NUM_TILES];
    __shared__ int   s_cnt;
    __shared__ ull   s_best;
    __shared__ float s_thr;
    __shared__ int   s_hasP, s_gt, s_cid;

    const int q    = blockIdx.x;
    const int tid  = threadIdx.x;
    const int lane = tid & 31;
    const int w    = tid >> 5;

    if (tid == 0) {
        s_cnt  = 0;
        s_best = ~0ULL;
        bool hasP = (g_aP[q] != ~0ULL);
        float amin = hasP ? decode_hi(g_aP[q]) : decode_hi(g_aF[q]);
        float m = 0.0078125f * 1.05f * sqrtf(g_a2[q] * __int_as_float(g_b2maxI)) + 0.02f;
        s_thr  = amin + 2.f * m;
        s_hasP = hasP ? 1 : 0;
        s_gt   = gt[q];
        s_cid  = cid[q];
    }
    __syncthreads();

    {   // coalesced tile scan
        const ull* tmins = (s_hasP ? g_tileP : g_tileF) + (size_t)q * NUM_TILES;
        for (int t = tid; t < NUM_TILES; t += 512) {
            ull tm = tmins[t];
            if (tm != ~0ULL && decode_hi(tm) <= s_thr) {
                int i = atomicAdd(&s_cnt, 1);
                s_tiles[i] = t;
            }
        }
    }
    __syncthreads();

    const int cnt = s_cnt;
    const float4* fa = (const float4*)(feat + (size_t)q * DD);
    const float4 qa0 = fa[lane * 2], qa1 = fa[lane * 2 + 1];

    for (int i = 0; i < cnt; ++i) {
        const int n0 = s_tiles[i] * TN;
#pragma unroll 1
        for (int r = w; r < TN; r += 16) {
            int n = n0 + r;
            if (n >= NBANK) continue;
            if (clsL[n] == s_gt) continue;
            if (s_hasP && cluL[n] != s_cid) continue;
            const float4* fb = (const float4*)(bank + (size_t)n * DD);
            float4 b0 = fb[lane * 2], b1 = fb[lane * 2 + 1];
            float d = 0.f;
            d = fmaf(qa0.x, b0.x, d); d = fmaf(qa0.y, b0.y, d);
            d = fmaf(qa0.z, b0.z, d); d = fmaf(qa0.w, b0.w, d);
            d = fmaf(qa1.x, b1.x, d); d = fmaf(qa1.y, b1.y, d);
            d = fmaf(qa1.z, b1.z, d); d = fmaf(qa1.w, b1.w, d);
#pragma unroll
            for (int o = 16; o; o >>= 1) d += __shfl_xor_sync(0xffffffffu, d, o);
            if (lane == 0)
                atomicMin(&s_best, encode(fmaf(-2.f, d, g_b2[n]), n));
        }
    }
    __syncthreads();

    {   // fused gather: winner row -> output
        ull e = s_best;
        int idx = (e == ~0ULL) ? 0 : (int)(u32)(e & 0xffffffffu);
        if (tid < 64) {
            const float4* src = (const float4*)(bank + (size_t)idx * DD);
            float4*       dst = (float4*)(out + (size_t)q * DD);
            dst[tid] = src[tid];
        }
    }
}

// ---------------------------------------------------------------------------
extern "C" void kernel_launch(void* const* d_in, const int* in_sizes, int n_in,
                              void* d_out, int out_size) {
    const float* feature = (const float*)d_in[0];
    const float* bank    = (const float*)d_in[1];
    const int*   cluL    = (const int*)d_in[2];
    const int*   clsL    = (const int*)d_in[3];
    const int*   cid     = (const int*)d_in[4];
    const int*   gtl     = (const int*)d_in[5];

    cudaFuncSetAttribute(main_kernel,
                         cudaFuncAttributeMaxDynamicSharedMemorySize, SMEM_TOTAL);

    prep_kernel<<<NCH, BQ>>>(feature);                                           // #1
    main_kernel<<<NUM_TILES, THREADS, SMEM_TOTAL>>>(bank, cluL, clsL, cid, gtl); // #2
    rescore_kernel<<<BQ, 512>>>(feature, bank, cluL, clsL, cid, gtl,
                                (float*)d_out);                                  // #3
}

// round 13
// speedup vs baseline: 2.0246x; 1.2513x over previous
#include <cuda_runtime.h>
#include <cuda_bf16.h>

#define BQ 256
#define DD 256
#define NBANK 100000
#define TN 128
#define NUM_TILES ((NBANK + TN - 1) / TN)      // 782
#define NCH 8
#define KCH 32
#define SR 80                                   // smem row stride (64B data + 16B pad)
#define THREADS 256

typedef unsigned long long ull;
typedef unsigned int u32;

// --------------- device scratch --------------------------------------------
__device__ ull    g_aP[BQ];
__device__ ull    g_aF[BQ];
__device__ float  g_a2[BQ];
__device__ int    g_b2maxI;
__device__ uint4  g_Q[NCH][BQ][4];              // hi-split queries (L2-resident)
__device__ float  g_b2[NBANK];
__device__ ull    g_tileP[(size_t)BQ * NUM_TILES];   // [q][tile]
__device__ ull    g_tileF[(size_t)BQ * NUM_TILES];

// --------------- smem layout -------------------------------------------------
#define QBUF  (BQ * SR)                     // 20480
#define BBUF  (TN * SR)                     // 10240
#define OFF_Q    0                          // [2 buf][256][SR]
#define OFF_B    (2 * QBUF)                 // 40960: [2 buf][128][SR]
#define OFF_RED  (OFF_B + 2 * BBUF)         // 61440
#define OFF_B2S  (OFF_RED + 2 * BQ * 8)     // 65536
#define OFF_SCLU (OFF_B2S + 512)
#define OFF_SCLS (OFF_SCLU + 512)
#define OFF_SCID (OFF_SCLS + 512)
#define OFF_SGT  (OFF_SCID + 1024)
#define SMEM_TOTAL (OFF_SGT + 1024)         // 69120

// --------------- helpers -----------------------------------------------------
__device__ __forceinline__ u32 smem_u32(const void* p) {
    u32 a;
    asm("{ .reg .u64 t; cvta.to.shared.u64 t, %1; cvt.u32.u64 %0, t; }" : "=r"(a) : "l"(p));
    return a;
}
#define LDSM_X4(r, addr) \
    asm volatile("ldmatrix.sync.aligned.m8n8.x4.shared.b16 {%0,%1,%2,%3}, [%4];" \
        : "=r"((r)[0]), "=r"((r)[1]), "=r"((r)[2]), "=r"((r)[3]) : "r"(addr))
#define MMA16816(d, a, b0, b1) \
    asm volatile("mma.sync.aligned.m16n8k16.row.col.f32.bf16.bf16.f32 " \
        "{%0,%1,%2,%3}, {%4,%5,%6,%7}, {%8,%9}, {%0,%1,%2,%3};" \
        : "+f"((d)[0]), "+f"((d)[1]), "+f"((d)[2]), "+f"((d)[3]) \
        : "r"((a)[0]), "r"((a)[1]), "r"((a)[2]), "r"((a)[3]), "r"(b0), "r"(b1))
#define CP_ASYNC16(dst, src) \
    asm volatile("cp.async.cg.shared.global [%0], [%1], 16;" :: "r"(dst), "l"(src) : "memory")
#define CP_COMMIT() asm volatile("cp.async.commit_group;" ::: "memory")
#define CP_WAIT0()  asm volatile("cp.async.wait_group 0;" ::: "memory")

__device__ __forceinline__ ull encode(float f, int n) {
    u32 u = __float_as_uint(f);
    u = (u & 0x80000000u) ? ~u : (u | 0x80000000u);
    return ((ull)u << 32) | (u32)n;
}
__device__ __forceinline__ float decode_hi(ull e) {
    u32 u = (u32)(e >> 32);
    u = (u & 0x80000000u) ? (u ^ 0x80000000u) : ~u;
    return __uint_as_float(u);
}
__device__ __forceinline__ u32 hi2(float a0, float a1) {
    __nv_bfloat16 h0 = __float2bfloat16(a0);
    __nv_bfloat16 h1 = __float2bfloat16(a1);
    return (u32)__bfloat16_as_ushort(h0) | ((u32)__bfloat16_as_ushort(h1) << 16);
}

// ---------------------------------------------------------------------------
// prep: one block per query, 128 threads. Thread t converts element pair
// (2t, 2t+1) -> one packed bf16x2 word in g_Q's [NCH][BQ][16]-u32 layout.
// Block-reduced exact-ish a2 (slack-covered). ~3us total.
// ---------------------------------------------------------------------------
__global__ void __launch_bounds__(128) prep_kernel(const float* __restrict__ feat) {
    const int q = blockIdx.x, t = threadIdx.x;
    const float2 v = ((const float2*)(feat + (size_t)q * DD))[t];   // coalesced
    ((u32*)g_Q)[(t >> 4) * (BQ * 16) + q * 16 + (t & 15)] = hi2(v.x, v.y);

    float s = fmaf(v.x, v.x, v.y * v.y);
#pragma unroll
    for (int o = 16; o; o >>= 1) s += __shfl_xor_sync(0xffffffffu, s, o);
    __shared__ float ws[4];
    if ((t & 31) == 0) ws[t >> 5] = s;
    __syncthreads();
    if (t == 0) {
        g_a2[q] = ws[0] + ws[1] + ws[2] + ws[3];
        g_aP[q] = ~0ULL;
        g_aF[q] = ~0ULL;
        if (q == 0) g_b2maxI = 0;
    }
}

// ---------------------------------------------------------------------------
__device__ __forceinline__ void stage_q(u32 smb, int buf, int c, int tid) {
#pragma unroll
    for (int p = 0; p < 4; ++p) {
        int idx = tid + THREADS * p;
        int row = idx >> 2, seg = idx & 3;
        CP_ASYNC16(smb + OFF_Q + (u32)buf * QBUF + (u32)row * SR + (u32)seg * 16,
                   &g_Q[c][row][seg]);
    }
}

__device__ __forceinline__ void ldB(const float* __restrict__ bank, int gn, int c,
                                    int half, float4* r) {
    if (gn < NBANK) {
        const float4* p = (const float4*)(bank + (size_t)gn * DD + c * KCH + half * 16);
        r[0] = p[0]; r[1] = p[1]; r[2] = p[2]; r[3] = p[3];
    } else {
        r[0] = r[1] = r[2] = r[3] = make_float4(0.f, 0.f, 0.f, 0.f);
    }
}
__device__ __forceinline__ float cvtB(const float4* r, char* dst) {
    float s = 0.f;
#pragma unroll
    for (int i = 0; i < 4; ++i) {
        s = fmaf(r[i].x, r[i].x, s); s = fmaf(r[i].y, r[i].y, s);
        s = fmaf(r[i].z, r[i].z, s); s = fmaf(r[i].w, r[i].w, s);
    }
    ((uint4*)dst)[0] = make_uint4(hi2(r[0].x, r[0].y), hi2(r[0].z, r[0].w),
                                  hi2(r[1].x, r[1].y), hi2(r[1].z, r[1].w));
    ((uint4*)dst)[1] = make_uint4(hi2(r[2].x, r[2].y), hi2(r[2].z, r[2].w),
                                  hi2(r[3].x, r[3].y), hi2(r[3].z, r[3].w));
    return s;
}

// ---------------------------------------------------------------------------
// Phase A: fused streaming convert + hi-only bf16 HMMA GEMM + masked dual
// argmin; per-(q,tile) minima out, exact b2 out.
// ---------------------------------------------------------------------------
__global__ void __launch_bounds__(THREADS, 1) main_kernel(
    const float* __restrict__ bank,
    const int* __restrict__ cluL, const int* __restrict__ clsL,
    const int* __restrict__ cid,  const int* __restrict__ gt)
{
    extern __shared__ char sm[];
    const u32 smb  = smem_u32(sm);
    const int tid  = threadIdx.x;
    const int lane = tid & 31;
    const int w    = tid >> 5;
    const int n0   = blockIdx.x * TN;

    ull*   redP = (ull*)(sm + OFF_RED);
    ull*   redF = redP + BQ;
    float* b2s  = (float*)(sm + OFF_B2S);
    int*   sClu = (int*)(sm + OFF_SCLU);
    int*   sCls = (int*)(sm + OFF_SCLS);
    int*   sCid = (int*)(sm + OFF_SCID);
    int*   sGt  = (int*)(sm + OFF_SGT);

    const int crow  = tid >> 1;
    const int chalf = tid & 1;
    const int cgn   = n0 + crow;
    float b2part = 0.f;

    stage_q(smb, 0, 0, tid);
    CP_COMMIT();
    {
        float4 r[4];
        ldB(bank, cgn, 0, chalf, r);
        b2part += cvtB(r, sm + OFF_B + crow * SR + chalf * 32);
    }

    redP[tid] = ~0ULL;
    redF[tid] = ~0ULL;
    sCid[tid] = cid[tid];
    sGt[tid]  = gt[tid];
    if (tid < TN) {
        int n = n0 + tid;
        bool v = (n < NBANK);
        sClu[tid] = v ? cluL[n] : -1;
        sCls[tid] = v ? clsL[n] : 0x7fffffff;
    }

    const int q0 = (w & 3) * 64;
    const int nh = (w >> 2) * 64;

    float acc[4][8][4];
#pragma unroll
    for (int mi = 0; mi < 4; mi++)
#pragma unroll
        for (int nt = 0; nt < 8; nt++)
#pragma unroll
            for (int r = 0; r < 4; r++) acc[mi][nt][r] = 0.f;

    const u32 aRowOff = (u32)(q0 + (lane & 15)) * SR + (u32)(lane >> 4) * 16;
    const int bRow    = nh + ((lane >> 4) & 1) * 8 + (lane & 7);
    const u32 bColB   = ((lane >> 3) & 1) * 16;

    CP_WAIT0();
    __syncthreads();

#pragma unroll 1
    for (int c = 0; c < NCH; ++c) {
        float4 pre[4];
        if (c + 1 < NCH) {
            ldB(bank, cgn, c + 1, chalf, pre);     // LDGs overlap MMAs below
            stage_q(smb, (c + 1) & 1, c + 1, tid);
            CP_COMMIT();
        }

        const u32 qH = smb + OFF_Q + (u32)(c & 1) * QBUF + aRowOff;
        const u32 bB0 = smb + OFF_B + (u32)(c & 1) * BBUF;
#pragma unroll
        for (int kk = 0; kk < KCH; kk += 16) {
            const u32 kb = (u32)kk * 2 + bColB;
            u32 aH[4][4];
#pragma unroll
            for (int mi = 0; mi < 4; mi++) LDSM_X4(aH[mi], qH + mi * 16 * SR + kk * 2);
            u32 bB[16];
#pragma unroll
            for (int p = 0; p < 4; p++)
                LDSM_X4(&bB[4 * p], bB0 + (u32)(bRow + p * 16) * SR + kb);
#pragma unroll
            for (int mi = 0; mi < 4; mi++)
#pragma unroll
                for (int nt = 0; nt < 8; nt++)
                    MMA16816(acc[mi][nt], aH[mi], bB[2 * nt], bB[2 * nt + 1]);
        }

        if (c + 1 < NCH)
            b2part += cvtB(pre, sm + OFF_B + ((c + 1) & 1) * BBUF + crow * SR + chalf * 32);

        CP_WAIT0();
        __syncthreads();
    }

    {
        float other = __shfl_xor_sync(0xffffffffu, b2part, 1);
        if (chalf == 0) {
            float tot = b2part + other;
            b2s[crow] = tot;
            if (cgn < NBANK) {
                g_b2[cgn] = tot;
                atomicMax(&g_b2maxI, __float_as_int(tot));
            }
        }
    }
    __syncthreads();

    // ---- epilogue: masked dual argmin from HMMA fragments ----
    {
        const int jb = nh + 2 * (lane & 3);
        float b2r[16]; int clsr[16], clur[16]; bool val[16];
#pragma unroll
        for (int ni = 0; ni < 8; ni++)
#pragma unroll
            for (int h = 0; h < 2; h++) {
                int j = jb + 8 * ni + h, x = ni * 2 + h;
                b2r[x]  = b2s[j];
                clsr[x] = sCls[j];
                clur[x] = sClu[j];
                val[x]  = (n0 + j) < NBANK;
            }
#pragma unroll
        for (int mi = 0; mi < 4; mi++) {
#pragma unroll
            for (int half = 0; half < 2; half++) {
                int r = q0 + mi * 16 + (lane >> 2) + 8 * half;
                int gtq = sGt[r], ciq = sCid[r];
                ull bp = ~0ULL, bf = ~0ULL;
#pragma unroll
                for (int ni = 0; ni < 8; ni++)
#pragma unroll
                    for (int h = 0; h < 2; h++) {
                        int x = ni * 2 + h;
                        if (!val[x] || clsr[x] == gtq) continue;
                        float score = fmaf(-2.f, acc[mi][ni][half * 2 + h], b2r[x]);
                        ull e = encode(score, n0 + jb + 8 * ni + h);
                        if (e < bf) bf = e;
                        if (clur[x] == ciq && e < bp) bp = e;
                    }
#pragma unroll
                for (int o = 1; o <= 2; o <<= 1) {
                    ull tp = __shfl_xor_sync(0xffffffffu, bp, o);
                    ull tf = __shfl_xor_sync(0xffffffffu, bf, o);
                    if (tp < bp) bp = tp;
                    if (tf < bf) bf = tf;
                }
                if ((lane & 3) == 0) {
                    if (bp != ~0ULL) atomicMin(&redP[r], bp);
                    if (bf != ~0ULL) atomicMin(&redF[r], bf);
                }
            }
        }
    }
    __syncthreads();
    {
        ull p = redP[tid], f = redF[tid];
        g_tileP[(size_t)tid * NUM_TILES + blockIdx.x] = p;
        g_tileF[(size_t)tid * NUM_TILES + blockIdx.x] = f;
        if (p != ~0ULL) atomicMin(&g_aP[tid], p);
        if (f != ~0ULL) atomicMin(&g_aF[tid], f);
    }
}

// ---------------------------------------------------------------------------
// Phase B (+gather): one block per query; certified tile pick, exact fp32
// rescore, winner written straight to output.
// ---------------------------------------------------------------------------
__global__ void __launch_bounds__(512) rescore_kernel(
    const float* __restrict__ feat, const float* __restrict__ bank,
    const int* __restrict__ cluL, const int* __restrict__ clsL,
    const int* __restrict__ cid,  const int* __restrict__ gt,
    float* __restrict__ out)
{
    __shared__ int   s_tiles[NUM_TILES];
    __shared__ int   s_cnt;
    __shared__ ull   s_best;
    __shared__ float s_thr;
    __shared__ int   s_hasP, s_gt, s_cid;

    const int q    = blockIdx.x;
    const int tid  = threadIdx.x;
    const int lane = tid & 31;
    const int w    = tid >> 5;

    if (tid == 0) {
        s_cnt  = 0;
        s_best = ~0ULL;
        bool hasP = (g_aP[q] != ~0ULL);
        float amin = hasP ? decode_hi(g_aP[q]) : decode_hi(g_aF[q]);
        float m = 0.0078125f * 1.05f * sqrtf(g_a2[q] * __int_as_float(g_b2maxI)) + 0.02f;
        s_thr  = amin + 2.f * m;
        s_hasP = hasP ? 1 : 0;
        s_gt   = gt[q];
        s_cid  = cid[q];
    }
    __syncthreads();

    {
        const ull* tmins = (s_hasP ? g_tileP : g_tileF) + (size_t)q * NUM_TILES;
        for (int t = tid; t < NUM_TILES; t += 512) {
            ull tm = tmins[t];
            if (tm != ~0ULL && decode_hi(tm) <= s_thr) {
                int i = atomicAdd(&s_cnt, 1);
                s_tiles[i] = t;
            }
        }
    }
    __syncthreads();

    const int cnt = s_cnt;
    const float4* fa = (const float4*)(feat + (size_t)q * DD);
    const float4 qa0 = fa[lane * 2], qa1 = fa[lane * 2 + 1];

    for (int i = 0; i < cnt; ++i) {
        const int n0 = s_tiles[i] * TN;
#pragma unroll 1
        for (int r = w; r < TN; r += 16) {
            int n = n0 + r;
            if (n >= NBANK) continue;
            if (clsL[n] == s_gt) continue;
            if (s_hasP && cluL[n] != s_cid) continue;
            const float4* fb = (const float4*)(bank + (size_t)n * DD);
            float4 b0 = fb[lane * 2], b1 = fb[lane * 2 + 1];
            float d = 0.f;
            d = fmaf(qa0.x, b0.x, d); d = fmaf(qa0.y, b0.y, d);
            d = fmaf(qa0.z, b0.z, d); d = fmaf(qa0.w, b0.w, d);
            d = fmaf(qa1.x, b1.x, d); d = fmaf(qa1.y, b1.y, d);
            d = fmaf(qa1.z, b1.z, d); d = fmaf(qa1.w, b1.w, d);
#pragma unroll
            for (int o = 16; o; o >>= 1) d += __shfl_xor_sync(0xffffffffu, d, o);
            if (lane == 0)
                atomicMin(&s_best, encode(fmaf(-2.f, d, g_b2[n]), n));
        }
    }
    __syncthreads();

    {
        ull e = s_best;
        int idx = (e == ~0ULL) ? 0 : (int)(u32)(e & 0xffffffffu);
        if (tid < 64) {
            const float4* src = (const float4*)(bank + (size_t)idx * DD);
            float4*       dst = (float4*)(out + (size_t)q * DD);
            dst[tid] = src[tid];
        }
    }
}

// ---------------------------------------------------------------------------
extern "C" void kernel_launch(void* const* d_in, const int* in_sizes, int n_in,
                              void* d_out, int out_size) {
    const float* feature = (const float*)d_in[0];
    const float* bank    = (const float*)d_in[1];
    const int*   cluL    = (const int*)d_in[2];
    const int*   clsL    = (const int*)d_in[3];
    const int*   cid     = (const int*)d_in[4];
    const int*   gtl     = (const int*)d_in[5];

    cudaFuncSetAttribute(main_kernel,
                         cudaFuncAttributeMaxDynamicSharedMemorySize, SMEM_TOTAL);

    prep_kernel<<<BQ, 128>>>(feature);                                           // #1
    main_kernel<<<NUM_TILES, THREADS, SMEM_TOTAL>>>(bank, cluL, clsL, cid, gtl); // #2
    rescore_kernel<<<BQ, 512>>>(feature, bank, cluL, clsL, cid, gtl,
                                (float*)d_out);                                  // #3
}

// round 14
// speedup vs baseline: 2.4701x; 1.2200x over previous
#include <cuda_runtime.h>
#include <cuda_bf16.h>

#define BQ 256
#define DD 256
#define NBANK 100000
#define TN 128
#define NUM_TILES ((NBANK + TN - 1) / TN)      // 782
#define NCH 8
#define KCH 32
#define SR 80                                   // smem row stride (64B data + 16B pad)
#define THREADS 512

typedef unsigned long long ull;
typedef unsigned int u32;

// --------------- device scratch --------------------------------------------
__device__ ull    g_aP[BQ];
__device__ ull    g_aF[BQ];
__device__ float  g_a2[BQ];
__device__ int    g_b2maxI;
__device__ uint4  g_Q[NCH][BQ][4];              // hi-split queries (L2-resident)
__device__ float  g_b2[NBANK];
__device__ ull    g_tileP[(size_t)BQ * NUM_TILES];   // [q][tile]
__device__ ull    g_tileF[(size_t)BQ * NUM_TILES];

// --------------- smem layout -------------------------------------------------
#define QBUF  (BQ * SR)                     // 20480
#define BBUF  (TN * SR)                     // 10240
#define OFF_Q    0                          // [2 buf][256][SR]
#define OFF_B    (2 * QBUF)                 // 40960: [2 buf][128][SR]
#define OFF_RED  (OFF_B + 2 * BBUF)         // 61440
#define OFF_B2S  (OFF_RED + 2 * BQ * 8)     // 65536
#define OFF_SCLU (OFF_B2S + 512)
#define OFF_SCLS (OFF_SCLU + 512)
#define OFF_SCID (OFF_SCLS + 512)
#define OFF_SGT  (OFF_SCID + 1024)
#define SMEM_TOTAL (OFF_SGT + 1024)         // 69120

// --------------- helpers -----------------------------------------------------
__device__ __forceinline__ u32 smem_u32(const void* p) {
    u32 a;
    asm("{ .reg .u64 t; cvta.to.shared.u64 t, %1; cvt.u32.u64 %0, t; }" : "=r"(a) : "l"(p));
    return a;
}
#define LDSM_X4(r, addr) \
    asm volatile("ldmatrix.sync.aligned.m8n8.x4.shared.b16 {%0,%1,%2,%3}, [%4];" \
        : "=r"((r)[0]), "=r"((r)[1]), "=r"((r)[2]), "=r"((r)[3]) : "r"(addr))
#define MMA16816(d, a, b0, b1) \
    asm volatile("mma.sync.aligned.m16n8k16.row.col.f32.bf16.bf16.f32 " \
        "{%0,%1,%2,%3}, {%4,%5,%6,%7}, {%8,%9}, {%0,%1,%2,%3};" \
        : "+f"((d)[0]), "+f"((d)[1]), "+f"((d)[2]), "+f"((d)[3]) \
        : "r"((a)[0]), "r"((a)[1]), "r"((a)[2]), "r"((a)[3]), "r"(b0), "r"(b1))
#define CP_ASYNC16(dst, src) \
    asm volatile("cp.async.cg.shared.global [%0], [%1], 16;" :: "r"(dst), "l"(src) : "memory")
#define CP_COMMIT() asm volatile("cp.async.commit_group;" ::: "memory")
#define CP_WAIT0()  asm volatile("cp.async.wait_group 0;" ::: "memory")

__device__ __forceinline__ ull encode(float f, int n) {
    u32 u = __float_as_uint(f);
    u = (u & 0x80000000u) ? ~u : (u | 0x80000000u);
    return ((ull)u << 32) | (u32)n;
}
__device__ __forceinline__ float decode_hi(ull e) {
    u32 u = (u32)(e >> 32);
    u = (u & 0x80000000u) ? (u ^ 0x80000000u) : ~u;
    return __uint_as_float(u);
}
__device__ __forceinline__ u32 hi2(float a0, float a1) {
    __nv_bfloat16 h0 = __float2bfloat16(a0);
    __nv_bfloat16 h1 = __float2bfloat16(a1);
    return (u32)__bfloat16_as_ushort(h0) | ((u32)__bfloat16_as_ushort(h1) << 16);
}

// ---------------------------------------------------------------------------
// prep: one block per query, 128 threads (unchanged from R13, 4.5us).
// ---------------------------------------------------------------------------
__global__ void __launch_bounds__(128) prep_kernel(const float* __restrict__ feat) {
    const int q = blockIdx.x, t = threadIdx.x;
    const float2 v = ((const float2*)(feat + (size_t)q * DD))[t];
    ((u32*)g_Q)[(t >> 4) * (BQ * 16) + q * 16 + (t & 15)] = hi2(v.x, v.y);

    float s = fmaf(v.x, v.x, v.y * v.y);
#pragma unroll
    for (int o = 16; o; o >>= 1) s += __shfl_xor_sync(0xffffffffu, s, o);
    __shared__ float ws[4];
    if ((t & 31) == 0) ws[t >> 5] = s;
    __syncthreads();
    if (t == 0) {
        g_a2[q] = ws[0] + ws[1] + ws[2] + ws[3];
        g_aP[q] = ~0ULL;
        g_aF[q] = ~0ULL;
        if (q == 0) g_b2maxI = 0;
    }
}

// ---------------------------------------------------------------------------
__device__ __forceinline__ void stage_q(u32 smb, int buf, int c, int tid) {
#pragma unroll
    for (int p = 0; p < 2; ++p) {              // 1024 pieces / 512 threads
        int idx = tid + THREADS * p;
        int row = idx >> 2, seg = idx & 3;
        CP_ASYNC16(smb + OFF_Q + (u32)buf * QBUF + (u32)row * SR + (u32)seg * 16,
                   &g_Q[c][row][seg]);
    }
}

// Load 8 fp32 (one chunk-quarter of a bank row); zero for pad rows.
__device__ __forceinline__ void ldB(const float* __restrict__ bank, int gn, int c,
                                    int quarter, float4* r) {
    if (gn < NBANK) {
        const float4* p = (const float4*)(bank + (size_t)gn * DD + c * KCH + quarter * 8);
        r[0] = p[0]; r[1] = p[1];
    } else {
        r[0] = r[1] = make_float4(0.f, 0.f, 0.f, 0.f);
    }
}
// Convert 8 fp32 -> bf16, store 16B to smem; return partial square-sum.
__device__ __forceinline__ float cvtB(const float4* r, char* dst) {
    float s = 0.f;
#pragma unroll
    for (int i = 0; i < 2; ++i) {
        s = fmaf(r[i].x, r[i].x, s); s = fmaf(r[i].y, r[i].y, s);
        s = fmaf(r[i].z, r[i].z, s); s = fmaf(r[i].w, r[i].w, s);
    }
    *(uint4*)dst = make_uint4(hi2(r[0].x, r[0].y), hi2(r[0].z, r[0].w),
                              hi2(r[1].x, r[1].y), hi2(r[1].z, r[1].w));
    return s;
}

// ---------------------------------------------------------------------------
// Phase A: 512 threads (16 warps), warp tile 32q x 64n; fused streaming
// convert + hi-only bf16 HMMA GEMM + masked dual argmin.
// ---------------------------------------------------------------------------
__global__ void __launch_bounds__(THREADS, 1) main_kernel(
    const float* __restrict__ bank,
    const int* __restrict__ cluL, const int* __restrict__ clsL,
    const int* __restrict__ cid,  const int* __restrict__ gt)
{
    extern __shared__ char sm[];
    const u32 smb  = smem_u32(sm);
    const int tid  = threadIdx.x;
    const int lane = tid & 31;
    const int w    = tid >> 5;
    const int n0   = blockIdx.x * TN;

    ull*   redP = (ull*)(sm + OFF_RED);
    ull*   redF = redP + BQ;
    float* b2s  = (float*)(sm + OFF_B2S);
    int*   sClu = (int*)(sm + OFF_SCLU);
    int*   sCls = (int*)(sm + OFF_SCLS);
    int*   sCid = (int*)(sm + OFF_SCID);
    int*   sGt  = (int*)(sm + OFF_SGT);

    // conversion ownership: thread -> (row, 8-float quarter)
    const int crow = tid >> 2;
    const int cq   = tid & 3;
    const int cgn  = n0 + crow;
    float b2part = 0.f;

    stage_q(smb, 0, 0, tid);
    CP_COMMIT();
    {
        float4 r[2];
        ldB(bank, cgn, 0, cq, r);
        b2part += cvtB(r, sm + OFF_B + crow * SR + cq * 16);
    }

    if (tid < BQ) {
        redP[tid] = ~0ULL;
        redF[tid] = ~0ULL;
        sCid[tid] = cid[tid];
        sGt[tid]  = gt[tid];
    }
    if (tid < TN) {
        int n = n0 + tid;
        bool v = (n < NBANK);
        sClu[tid] = v ? cluL[n] : -1;
        sCls[tid] = v ? clsL[n] : 0x7fffffff;
    }

    // Warp tiling: 8 q-groups x 2 n-halves. 32q x 64n per warp.
    const int q0 = (w & 7) * 32;
    const int nh = (w >> 3) * 64;

    float acc[2][8][4];
#pragma unroll
    for (int mi = 0; mi < 2; mi++)
#pragma unroll
        for (int nt = 0; nt < 8; nt++)
#pragma unroll
            for (int r = 0; r < 4; r++) acc[mi][nt][r] = 0.f;

    const u32 aRowOff = (u32)(q0 + (lane & 15)) * SR + (u32)(lane >> 4) * 16;
    const int bRow    = nh + ((lane >> 4) & 1) * 8 + (lane & 7);
    const u32 bColB   = ((lane >> 3) & 1) * 16;

    CP_WAIT0();
    __syncthreads();                          // chunk 0 (Q + B) resident

#pragma unroll 1
    for (int c = 0; c < NCH; ++c) {
        float4 pre[2];
        if (c + 1 < NCH) {
            ldB(bank, cgn, c + 1, cq, pre);   // LDGs overlap MMAs below
            stage_q(smb, (c + 1) & 1, c + 1, tid);
            CP_COMMIT();
        }

        const u32 qH  = smb + OFF_Q + (u32)(c & 1) * QBUF + aRowOff;
        const u32 bB0 = smb + OFF_B + (u32)(c & 1) * BBUF;
#pragma unroll
        for (int kk = 0; kk < KCH; kk += 16) {
            const u32 kb = (u32)kk * 2 + bColB;
            u32 aH[2][4];
#pragma unroll
            for (int mi = 0; mi < 2; mi++) LDSM_X4(aH[mi], qH + mi * 16 * SR + kk * 2);
            u32 bB[16];
#pragma unroll
            for (int p = 0; p < 4; p++)
                LDSM_X4(&bB[4 * p], bB0 + (u32)(bRow + p * 16) * SR + kb);
#pragma unroll
            for (int mi = 0; mi < 2; mi++)
#pragma unroll
                for (int nt = 0; nt < 8; nt++)
                    MMA16816(acc[mi][nt], aH[mi], bB[2 * nt], bB[2 * nt + 1]);
        }

        if (c + 1 < NCH)
            b2part += cvtB(pre, sm + OFF_B + ((c + 1) & 1) * BBUF + crow * SR + cq * 16);

        CP_WAIT0();
        __syncthreads();
    }

    // finalize exact b2 per row (reduce across the 4 quarters)
    {
        b2part += __shfl_xor_sync(0xffffffffu, b2part, 1);
        b2part += __shfl_xor_sync(0xffffffffu, b2part, 2);
        if (cq == 0) {
            b2s[crow] = b2part;
            if (cgn < NBANK) {
                g_b2[cgn] = b2part;
                atomicMax(&g_b2maxI, __float_as_int(b2part));
            }
        }
    }
    __syncthreads();

    // ---- epilogue: masked dual argmin from HMMA fragments ----
    {
        const int jb = nh + 2 * (lane & 3);
        float b2r[16]; int clsr[16], clur[16]; bool val[16];
#pragma unroll
        for (int ni = 0; ni < 8; ni++)
#pragma unroll
            for (int h = 0; h < 2; h++) {
                int j = jb + 8 * ni + h, x = ni * 2 + h;
                b2r[x]  = b2s[j];
                clsr[x] = sCls[j];
                clur[x] = sClu[j];
                val[x]  = (n0 + j) < NBANK;
            }
#pragma unroll
        for (int mi = 0; mi < 2; mi++) {
#pragma unroll
            for (int half = 0; half < 2; half++) {
                int r = q0 + mi * 16 + (lane >> 2) + 8 * half;
                int gtq = sGt[r], ciq = sCid[r];
                ull bp = ~0ULL, bf = ~0ULL;
#pragma unroll
                for (int ni = 0; ni < 8; ni++)
#pragma unroll
                    for (int h = 0; h < 2; h++) {
                        int x = ni * 2 + h;
                        if (!val[x] || clsr[x] == gtq) continue;
                        float score = fmaf(-2.f, acc[mi][ni][half * 2 + h], b2r[x]);
                        ull e = encode(score, n0 + jb + 8 * ni + h);
                        if (e < bf) bf = e;
                        if (clur[x] == ciq && e < bp) bp = e;
                    }
#pragma unroll
                for (int o = 1; o <= 2; o <<= 1) {
                    ull tp = __shfl_xor_sync(0xffffffffu, bp, o);
                    ull tf = __shfl_xor_sync(0xffffffffu, bf, o);
                    if (tp < bp) bp = tp;
                    if (tf < bf) bf = tf;
                }
                if ((lane & 3) == 0) {
                    if (bp != ~0ULL) atomicMin(&redP[r], bp);
                    if (bf != ~0ULL) atomicMin(&redF[r], bf);
                }
            }
        }
    }
    __syncthreads();
    if (tid < BQ) {
        ull p = redP[tid], f = redF[tid];
        g_tileP[(size_t)tid * NUM_TILES + blockIdx.x] = p;
        g_tileF[(size_t)tid * NUM_TILES + blockIdx.x] = f;
        if (p != ~0ULL) atomicMin(&g_aP[tid], p);
        if (f != ~0ULL) atomicMin(&g_aF[tid], f);
    }
}

// ---------------------------------------------------------------------------
// Phase B (+gather): one block per query; certified tile pick, exact fp32
// rescore, winner written straight to output.
// ---------------------------------------------------------------------------
__global__ void __launch_bounds__(512) rescore_kernel(
    const float* __restrict__ feat, const float* __restrict__ bank,
    const int* __restrict__ cluL, const int* __restrict__ clsL,
    const int* __restrict__ cid,  const int* __restrict__ gt,
    float* __restrict__ out)
{
    __shared__ int   s_tiles[NUM_TILES];
    __shared__ int   s_cnt;
    __shared__ ull   s_best;
    __shared__ float s_thr;
    __shared__ int   s_hasP, s_gt, s_cid;

    const int q    = blockIdx.x;
    const int tid  = threadIdx.x;
    const int lane = tid & 31;
    const int w    = tid >> 5;

    if (tid == 0) {
        s_cnt  = 0;
        s_best = ~0ULL;
        bool hasP = (g_aP[q] != ~0ULL);
        float amin = hasP ? decode_hi(g_aP[q]) : decode_hi(g_aF[q]);
        float m = 0.0078125f * 1.05f * sqrtf(g_a2[q] * __int_as_float(g_b2maxI)) + 0.02f;
        s_thr  = amin + 2.f * m;
        s_hasP = hasP ? 1 : 0;
        s_gt   = gt[q];
        s_cid  = cid[q];
    }
    __syncthreads();

    {
        const ull* tmins = (s_hasP ? g_tileP : g_tileF) + (size_t)q * NUM_TILES;
        for (int t = tid; t < NUM_TILES; t += 512) {
            ull tm = tmins[t];
            if (tm != ~0ULL && decode_hi(tm) <= s_thr) {
                int i = atomicAdd(&s_cnt, 1);
                s_tiles[i] = t;
            }
        }
    }
    __syncthreads();

    const int cnt = s_cnt;
    const float4* fa = (const float4*)(feat + (size_t)q * DD);
    const float4 qa0 = fa[lane * 2], qa1 = fa[lane * 2 + 1];

    for (int i = 0; i < cnt; ++i) {
        const int n0 = s_tiles[i] * TN;
#pragma unroll 1
        for (int r = w; r < TN; r += 16) {
            int n = n0 + r;
            if (n >= NBANK) continue;
            if (clsL[n] == s_gt) continue;
            if (s_hasP && cluL[n] != s_cid) continue;
            const float4* fb = (const float4*)(bank + (size_t)n * DD);
            float4 b0 = fb[lane * 2], b1 = fb[lane * 2 + 1];
            float d = 0.f;
            d = fmaf(qa0.x, b0.x, d); d = fmaf(qa0.y, b0.y, d);
            d = fmaf(qa0.z, b0.z, d); d = fmaf(qa0.w, b0.w, d);
            d = fmaf(qa1.x, b1.x, d); d = fmaf(qa1.y, b1.y, d);
            d = fmaf(qa1.z, b1.z, d); d = fmaf(qa1.w, b1.w, d);
#pragma unroll
            for (int o = 16; o; o >>= 1) d += __shfl_xor_sync(0xffffffffu, d, o);
            if (lane == 0)
                atomicMin(&s_best, encode(fmaf(-2.f, d, g_b2[n]), n));
        }
    }
    __syncthreads();

    {
        ull e = s_best;
        int idx = (e == ~0ULL) ? 0 : (int)(u32)(e & 0xffffffffu);
        if (tid < 64) {
            const float4* src = (const float4*)(bank + (size_t)idx * DD);
            float4*       dst = (float4*)(out + (size_t)q * DD);
            dst[tid] = src[tid];
        }
    }
}

// ---------------------------------------------------------------------------
extern "C" void kernel_launch(void* const* d_in, const int* in_sizes, int n_in,
                              void* d_out, int out_size) {
    const float* feature = (const float*)d_in[0];
    const float* bank    = (const float*)d_in[1];
    const int*   cluL    = (const int*)d_in[2];
    const int*   clsL    = (const int*)d_in[3];
    const int*   cid     = (const int*)d_in[4];
    const int*   gtl     = (const int*)d_in[5];

    cudaFuncSetAttribute(main_kernel,
                         cudaFuncAttributeMaxDynamicSharedMemorySize, SMEM_TOTAL);

    prep_kernel<<<BQ, 128>>>(feature);                                           // #1
    main_kernel<<<NUM_TILES, THREADS, SMEM_TOTAL>>>(bank, cluL, clsL, cid, gtl); // #2
    rescore_kernel<<<BQ, 512>>>(feature, bank, cluL, clsL, cid, gtl,
                                (float*)d_out);                                  // #3
}